// round 14
// baseline (speedup 1.0000x reference)
#include <cuda_runtime.h>
#include <cuda_bf16.h>
#include <cstdint>

#define NPTS 4096
#define BATCH 8
#define MNODE 256
#define J3N (3*NPTS)            // 12288 stacked points per batch
#define PTOT (BATCH*J3N)        // 98304
#define P2   (BATCH*MNODE)      // 2048

// -------------------- scratch (static device globals; no allocation) -----
__device__ __align__(16) float g_counts[BATCH*MNODE];
__device__ __align__(16) float g_sums[BATCH*3*MNODE];
__device__ __align__(16) int   g_minidx[BATCH*J3N];
__device__ __align__(16) float g_bufB[384*PTOT];       // L4 fp32 out, 151 MB
__device__ __align__(16) float g_finalin[387*P2];
__device__ __align__(16) float g_fnB[1024*P2];
// bf16 hi/lo activation planes
__device__ __align__(16) uint16_t g_h1[256*PTOT], g_l1[256*PTOT];
__device__ __align__(16) uint16_t g_h2[256*PTOT], g_l2[256*PTOT];
__device__ __align__(16) uint16_t g_xh[3*PTOT],   g_xl[3*PTOT];
__device__ __align__(16) uint16_t g_finh[387*P2], g_finl[387*P2];
__device__ __align__(16) uint16_t g_nh1[768*P2],  g_nl1[768*P2];
__device__ __align__(16) uint16_t g_nh2[512*P2],  g_nl2[512*P2];
// bf16 hi/lo weight planes (zero-padded K)
#define WTOT 2232320
__device__ __align__(16) uint16_t g_wh[WTOT];
__device__ __align__(16) uint16_t g_wl[WTOT];

// ==================== helpers ============================================
__device__ __forceinline__ uint32_t smem_u32(const void* p) {
    uint32_t a;
    asm("{ .reg .u64 t; cvta.to.shared.u64 t, %1; cvt.u32.u64 %0, t; }"
        : "=r"(a) : "l"(p));
    return a;
}
#define CPASYNC(saddr, gptr) \
    asm volatile("cp.async.cg.shared.global [%0], [%1], 16;" \
                 :: "r"(saddr), "l"(gptr))
#define CPCOMMIT() asm volatile("cp.async.commit_group;")
#define CPWAIT(N)  asm volatile("cp.async.wait_group %0;" :: "n"(N))

#define LDSM4(r, addr) asm volatile( \
    "ldmatrix.sync.aligned.m8n8.x4.shared.b16 {%0,%1,%2,%3}, [%4];" \
    : "=r"((r)[0]),"=r"((r)[1]),"=r"((r)[2]),"=r"((r)[3]) : "r"(addr))
#define LDSM4T(r, addr) asm volatile( \
    "ldmatrix.sync.aligned.m8n8.x4.trans.shared.b16 {%0,%1,%2,%3}, [%4];" \
    : "=r"((r)[0]),"=r"((r)[1]),"=r"((r)[2]),"=r"((r)[3]) : "r"(addr))
#define MMA_BF16(c, a, b0, b1) asm volatile( \
    "mma.sync.aligned.m16n8k16.row.col.f32.bf16.bf16.f32 " \
    "{%0,%1,%2,%3}, {%4,%5,%6,%7}, {%8,%9}, {%0,%1,%2,%3};" \
    : "+f"((c)[0]),"+f"((c)[1]),"+f"((c)[2]),"+f"((c)[3]) \
    : "r"((a)[0]),"r"((a)[1]),"r"((a)[2]),"r"((a)[3]), "r"(b0),"r"(b1))

__device__ __forceinline__ void split1(float v, uint16_t& h, uint16_t& l) {
    __nv_bfloat16 hb = __float2bfloat16_rn(v);
    h = __bfloat16_as_ushort(hb);
    l = __bfloat16_as_ushort(__float2bfloat16_rn(v - __bfloat162float(hb)));
}

// ==================== prep: zero accumulators + weight split (one launch) =
// Weight planes for tensor layers live at offsets >= 8192 (layer0 is fp32
// in l1x2). Grid covers WREST; zeroing ranges are smaller subsets.
#define ZTOT (387*P2)
#define WREST (WTOT - 8192)
__global__ void prep_kernel(const float* __restrict__ w1,
                            const float* __restrict__ w2, const float* __restrict__ w3,
                            const float* __restrict__ w4, const float* __restrict__ w5,
                            const float* __restrict__ w6)
{
    int i = blockIdx.x * 256 + threadIdx.x;
    if (i < BATCH*MNODE) g_counts[i] = 0.f;
    if (i < BATCH*3*MNODE) g_sums[i] = 0.f;
    if (i < ZTOT) g_finalin[i] = 0.f;
    int wi = i + 8192;
    if (wi >= WTOT) return;
    const float* W; int K, Kpad, off;
    if      (wi <   40960) { W = w1; K =  128; Kpad =  128; off = 8192; }
    else if (wi <  151552) { W = w2; K =  259; Kpad =  288; off = 40960; }
    else if (wi <  364544) { W = w3; K =  387; Kpad =  416; off = 151552; }
    else if (wi <  626688) { W = w4; K =  512; Kpad =  512; off = 364544; }
    else if (wi < 1019904) { W = w5; K =  512; Kpad =  512; off = 626688; }
    else                   { W = w6; K = 1155; Kpad = 1184; off = 1019904; }
    int li = wi - off;
    int m = li / Kpad, k = li % Kpad;
    float v = (k < K) ? W[(size_t)m * K + k] : 0.f;
    split1(v, g_wh[wi], g_wl[wi]);
}

__global__ void fsplit_kernel(const float* __restrict__ X,
                              uint16_t* __restrict__ H, uint16_t* __restrict__ L,
                              int n)
{
    int i = blockIdx.x * 256 + threadIdx.x;
    if (i >= n) return;
    split1(X[i], H[i], L[i]);
}

// ==================== mma.sync bf16 split GEMM (2-stage, 1 sync/tile) =====
// Y[M,P] = relu(W @ X + bias). Tile BM x BN, BK=32. 8 warps as 2 x 4.
// epi: 0 = write hi/lo bf16 planes (Yh/Yl); 1 = write fp32 plane (Yf)
template<int BM, int BN>
__global__ void __launch_bounds__(256, 2)
mlp_mma(const uint16_t* __restrict__ Wh, const uint16_t* __restrict__ Wl, int Kpad,
        const float* __restrict__ bias,
        const uint16_t* __restrict__ XH1, const uint16_t* __restrict__ XL1, int C1,
        const uint16_t* __restrict__ XH2, const uint16_t* __restrict__ XL2,
        float* __restrict__ Yf, uint16_t* __restrict__ Yh, uint16_t* __restrict__ Yl,
        int Kd, int P, int epi)
{
    constexpr int MI = BM / 32;            // m16-frags per warp (warp_m dim 2)
    constexpr int NG = BN / 64;            // LDSM4T groups per plane
    constexpr int NI = 2 * NG;             // n8-frag pairs
    constexpr int APLANE = BM * 80;        // BM*40*2 bytes (stride 40 uint16)
    constexpr int BSTR = BN + 8;           // B row stride in uint16
    constexpr int BPLANE = 32 * BSTR * 2;
    constexpr int BOFF = 2 * APLANE;
    constexpr int STAGE = 2 * APLANE + 2 * BPLANE;
    constexpr int AITER = BM / 64;
    constexpr int BITER = BN / 64;
    constexpr int BCH = BN / 8;            // 16B chunks per B row

    extern __shared__ __align__(16) char dyn[];
    const int tid = threadIdx.x, lane = tid & 31, wid = tid >> 5;
    const int warp_m = wid & 1, warp_n = wid >> 1;   // 2 x 4 warp grid
    const int tile_m = blockIdx.y * BM;
    const int tile_p = blockIdx.x * BN;
    const uint32_t sbase = smem_u32(dyn);

    float acc[MI][NI][4] = {};
    const int nt = Kpad / 32;

    auto fill = [&](int stg, int t) {
        const int k0 = t * 32;
        const uint32_t st = sbase + stg * STAGE;
#pragma unroll
        for (int i = 0; i < AITER; i++) {
            int e = tid + i * 256;
            int m = e >> 2, c = e & 3;
            uint32_t d = st + (uint32_t)(m * 80 + c * 16);
            size_t go = (size_t)(tile_m + m) * Kpad + k0 + c * 8;
            CPASYNC(d, Wh + go);
            CPASYNC(d + APLANE, Wl + go);
        }
#pragma unroll
        for (int i = 0; i < BITER; i++) {
            int e = tid + i * 256;
            int k = e / BCH, c = e % BCH;
            int gk = k0 + k;
            uint32_t d = st + BOFF + (uint32_t)(k * BSTR + c * 8) * 2;
            if (gk < Kd) {
                const uint16_t* sh = ((gk < C1) ? XH1 + (size_t)gk * P
                                                : XH2 + (size_t)(gk - C1) * P)
                                     + tile_p + c * 8;
                const uint16_t* sl = ((gk < C1) ? XL1 + (size_t)gk * P
                                                : XL2 + (size_t)(gk - C1) * P)
                                     + tile_p + c * 8;
                CPASYNC(d, sh);
                CPASYNC(d + BPLANE, sl);
            } else {
                *(uint4*)(dyn + (d - sbase)) = make_uint4(0, 0, 0, 0);
                *(uint4*)(dyn + (d + BPLANE - sbase)) = make_uint4(0, 0, 0, 0);
            }
        }
        CPCOMMIT();
    };

    auto compute = [&](int stg) {
        const uint32_t st = sbase + stg * STAGE;
#pragma unroll
        for (int kc = 0; kc < 32; kc += 16) {
            uint32_t bh[NG][4], bl[NG][4];
            uint32_t brow = (uint32_t)(kc + (lane & 7) + ((lane >> 3) & 1) * 8);
#pragma unroll
            for (int g = 0; g < NG; g++) {
                uint32_t bcol = (uint32_t)(warp_n * (BN/4) + g * 16 + (lane >> 4) * 8);
                uint32_t ba = st + BOFF + (brow * BSTR + bcol) * 2;
                LDSM4T(bh[g], ba);
                LDSM4T(bl[g], ba + BPLANE);
            }
#pragma unroll
            for (int mi = 0; mi < MI; mi++) {
                uint32_t ar = (uint32_t)(warp_m * (BM/2) + mi * 16 + (lane & 15));
                uint32_t ac = (uint32_t)(kc + (lane >> 4) * 8);
                uint32_t aa = st + (ar * 40 + ac) * 2;
                uint32_t ah[4], al[4];
                LDSM4(ah, aa);
                LDSM4(al, aa + APLANE);
#pragma unroll
                for (int ni = 0; ni < NI; ni++) {
                    int g = ni >> 1, x = (ni & 1) * 2;
                    MMA_BF16(acc[mi][ni], ah, bh[g][x], bh[g][x + 1]);
                    MMA_BF16(acc[mi][ni], ah, bl[g][x], bl[g][x + 1]);
                    MMA_BF16(acc[mi][ni], al, bh[g][x], bh[g][x + 1]);
                }
            }
        }
    };

    // 2-stage, single sync per k-tile: the sync at iter t orders
    // compute(t-1) (buffer cur^1) before fill(t+1) overwrites it; CPWAIT(0)
    // + sync makes fill(t)'s data visible to all threads for compute(t).
    fill(0, 0);
    for (int t = 0; t < nt; t++) {
        const int cur = t & 1;
        CPWAIT(0);
        __syncthreads();
        if (t + 1 < nt) fill(cur ^ 1, t + 1);
        compute(cur);
    }

    // ---- epilogue ----
#pragma unroll
    for (int mi = 0; mi < MI; mi++) {
        int gm0 = tile_m + warp_m * (BM/2) + mi * 16 + (lane >> 2);
        float b0 = bias[gm0], b1 = bias[gm0 + 8];
#pragma unroll
        for (int ni = 0; ni < NI; ni++) {
            int gp = tile_p + warp_n * (BN/4) + ni * 8 + (lane & 3) * 2;
            float* c = acc[mi][ni];
            float v00 = fmaxf(c[0] + b0, 0.f), v01 = fmaxf(c[1] + b0, 0.f);
            float v10 = fmaxf(c[2] + b1, 0.f), v11 = fmaxf(c[3] + b1, 0.f);
            if (epi == 1) {
                *(float2*)(Yf + (size_t)gm0 * P + gp) = make_float2(v00, v01);
                *(float2*)(Yf + (size_t)(gm0 + 8) * P + gp) = make_float2(v10, v11);
            } else {
                uint16_t h0, l0, h1_, l1_;
                split1(v00, h0, l0); split1(v01, h1_, l1_);
                *(uint32_t*)(Yh + (size_t)gm0 * P + gp) =
                    (uint32_t)h0 | ((uint32_t)h1_ << 16);
                *(uint32_t*)(Yl + (size_t)gm0 * P + gp) =
                    (uint32_t)l0 | ((uint32_t)l1_ << 16);
                split1(v10, h0, l0); split1(v11, h1_, l1_);
                *(uint32_t*)(Yh + (size_t)(gm0 + 8) * P + gp) =
                    (uint32_t)h0 | ((uint32_t)h1_ << 16);
                *(uint32_t*)(Yl + (size_t)(gm0 + 8) * P + gp) =
                    (uint32_t)l0 | ((uint32_t)l1_ << 16);
            }
        }
    }
}

#define SMEM_P (2*(2*(128*80) + 2*(32*136*2)))
#define SMEM_N (2*(2*(64*80)  + 2*(32*72*2)))

// ==================== KNN + scatter counts/sums ===========================
__global__ void knn_kernel(const float* __restrict__ x,
                           const float* __restrict__ node)
{
    int b = blockIdx.y;
    int n = blockIdx.x * blockDim.x + threadIdx.x;
    __shared__ float s0[MNODE], s1[MNODE], s2[MNODE], sq[MNODE];
    for (int m = threadIdx.x; m < MNODE; m += blockDim.x) {
        float a = node[(b*3+0)*MNODE + m];
        float bb = node[(b*3+1)*MNODE + m];
        float c = node[(b*3+2)*MNODE + m];
        s0[m] = a; s1[m] = bb; s2[m] = c;
        sq[m] = a*a + bb*bb + c*c;
    }
    __syncthreads();
    if (n >= NPTS) return;
    float x0 = x[(b*3+0)*NPTS + n];
    float x1 = x[(b*3+1)*NPTS + n];
    float x2 = x[(b*3+2)*NPTS + n];
    float xx = x0*x0 + x1*x1 + x2*x2;
    float bd0 = 1e30f, bd1 = 1e30f, bd2 = 1e30f;
    int bi0 = 0, bi1 = 0, bi2 = 0;
    for (int m = 0; m < MNODE; m++) {
        float cr = x0*s0[m] + x1*s1[m] + x2*s2[m];
        float d = (xx + sq[m]) - 2.0f*cr;
        if (d < bd0)      { bd2=bd1; bi2=bi1; bd1=bd0; bi1=bi0; bd0=d; bi0=m; }
        else if (d < bd1) { bd2=bd1; bi2=bi1; bd1=d; bi1=m; }
        else if (d < bd2) { bd2=d; bi2=m; }
    }
    int base = b*J3N + n;
    g_minidx[base]          = bi0;
    g_minidx[base + NPTS]   = bi1;
    g_minidx[base + 2*NPTS] = bi2;
    int mm[3] = {bi0, bi1, bi2};
#pragma unroll
    for (int k = 0; k < 3; k++) {
        atomicAdd(&g_counts[b*MNODE + mm[k]], 1.0f);
        atomicAdd(&g_sums[(b*3+0)*MNODE + mm[k]], x0);
        atomicAdd(&g_sums[(b*3+1)*MNODE + mm[k]], x1);
        atomicAdd(&g_sums[(b*3+2)*MNODE + mm[k]], x2);
    }
}

// ==================== fused xdec + L1 + L2 (fp32) =========================
__global__ void __launch_bounds__(256) l1x2_kernel(
    const float* __restrict__ x,
    const float* __restrict__ W1, const float* __restrict__ B1,
    const float* __restrict__ W2, const float* __restrict__ B2)
{
    __shared__ float w1[64*3];
    __shared__ float b1s[64];
    __shared__ float b2s[128];
    __shared__ float w2[128*64];        // 32 KB
    int tid = threadIdx.x;
    if (tid < 192) w1[tid] = W1[tid];
    if (tid < 64)  b1s[tid] = B1[tid];
    if (tid < 128) b2s[tid] = B2[tid];
    for (int i = tid; i < 128*64; i += 256) w2[i] = W2[i];
    __syncthreads();

    int p = blockIdx.x * 256 + tid;
    int b = p / J3N, j = p % J3N, n = j % NPTS;
    int m = g_minidx[p];
    float den = g_counts[b*MNODE + m] + 1e-5f;
    float v0 = x[(b*3+0)*NPTS + n] - g_sums[(b*3+0)*MNODE + m] / den;
    float v1 = x[(b*3+1)*NPTS + n] - g_sums[(b*3+1)*MNODE + m] / den;
    float v2 = x[(b*3+2)*NPTS + n] - g_sums[(b*3+2)*MNODE + m] / den;
    split1(v0, g_xh[p],          g_xl[p]);
    split1(v1, g_xh[PTOT + p],   g_xl[PTOT + p]);
    split1(v2, g_xh[2*PTOT + p], g_xl[2*PTOT + p]);

    float v[64];
#pragma unroll
    for (int c = 0; c < 64; c++) {
        float s = fmaf(w1[c*3+0], v0, fmaf(w1[c*3+1], v1, fmaf(w1[c*3+2], v2, b1s[c])));
        v[c] = fmaxf(s, 0.f);
    }
    for (int o = 0; o < 128; o++) {
        float s = b2s[o];
        const float* wr = &w2[o * 64];
#pragma unroll
        for (int c = 0; c < 64; c++) s = fmaf(wr[c], v[c], s);
        s = fmaxf(s, 0.f);
        split1(s, g_h2[(size_t)o*PTOT + p], g_l2[(size_t)o*PTOT + p]);
    }
}

// ==================== cluster mean into finalin rows 0..2 =================
__global__ void meanfin_kernel()
{
    int i = blockIdx.x * blockDim.x + threadIdx.x;
    if (i >= BATCH*MNODE) return;
    int b = i / MNODE, m = i % MNODE;
    float den = g_counts[i] + 1e-5f;
#pragma unroll
    for (int c = 0; c < 3; c++)
        g_finalin[c*P2 + i] = g_sums[(b*3+c)*MNODE + m] / den;
}

// ==================== segment max, smem-staged (4096 pts/CTA) =============
__global__ void segmax2_kernel()
{
    __shared__ int sm[MNODE*16];
    int tid = threadIdx.x;
    for (int e = tid; e < MNODE*16; e += 256) sm[e] = 0;
    __syncthreads();
    int c0 = blockIdx.y * 16;
    int pbase = blockIdx.x * 4096;
    int b = pbase / J3N;
    for (int pp = tid; pp < 4096; pp += 256) {
        int p = pbase + pp;
        int m = g_minidx[p];
#pragma unroll
        for (int c = 0; c < 16; c++) {
            float v = g_bufB[(size_t)(c0+c)*PTOT + p];
            atomicMax(&sm[m*16+c], __float_as_int(v));
        }
    }
    __syncthreads();
    for (int e = tid; e < MNODE*16; e += 256) {
        int v = sm[e];
        if (v != 0) {
            int m = e / 16, c = e % 16;
            atomicMax((int*)&g_finalin[(size_t)(3+c0+c)*P2 + b*MNODE + m], v);
        }
    }
}

__global__ void fallback_kernel()
{
    int t = blockIdx.x * blockDim.x + threadIdx.x;
    if (t >= BATCH*MNODE*384) return;
    int c  = t / (BATCH*MNODE);
    int i2 = t % (BATCH*MNODE);
    if (g_counts[i2] > 0.f) return;
    int b = i2 / MNODE;
    g_finalin[(size_t)(3 + c)*P2 + i2] = g_bufB[(size_t)c*PTOT + (size_t)b*J3N];
}

__global__ void outmax_kernel(float* __restrict__ out)
{
    int gt = blockIdx.x * blockDim.x + threadIdx.x;
    int w = gt >> 5;
    int lane = gt & 31;
    if (w >= BATCH*1024) return;
    int b = w / 1024, c = w % 1024;
    const float* src = &g_fnB[(size_t)c*P2 + b*MNODE];
    float v = -1e30f;
#pragma unroll
    for (int i = lane; i < MNODE; i += 32) v = fmaxf(v, src[i]);
#pragma unroll
    for (int o = 16; o > 0; o >>= 1)
        v = fmaxf(v, __shfl_xor_sync(0xffffffffu, v, o));
    if (lane == 0) out[w] = v;
}

// ==========================================================================
extern "C" void kernel_launch(void* const* d_in, const int* in_sizes, int n_in,
                              void* d_out, int out_size)
{
    const float* x    = (const float*)d_in[0];
    const float* node = (const float*)d_in[2];
    const float* fp_w[4] = {(const float*)d_in[4], (const float*)d_in[6],
                            (const float*)d_in[8], (const float*)d_in[10]};
    const float* fp_b[4] = {(const float*)d_in[5], (const float*)d_in[7],
                            (const float*)d_in[9], (const float*)d_in[11]};
    const float* fn_w[4] = {(const float*)d_in[12], (const float*)d_in[14],
                            (const float*)d_in[16], (const float*)d_in[18]};
    const float* fn_b[4] = {(const float*)d_in[13], (const float*)d_in[15],
                            (const float*)d_in[17], (const float*)d_in[19]};
    float* out = (float*)d_out;

    float *finalin, *bufB, *fnB;
    uint16_t *wh, *wl, *h1, *l1, *h2, *l2, *xh, *xl, *finh, *finl;
    uint16_t *nh1, *nl1, *nh2, *nl2;
    cudaGetSymbolAddress((void**)&finalin, g_finalin);
    cudaGetSymbolAddress((void**)&bufB,    g_bufB);
    cudaGetSymbolAddress((void**)&fnB,     g_fnB);
    cudaGetSymbolAddress((void**)&wh,      g_wh);
    cudaGetSymbolAddress((void**)&wl,      g_wl);
    cudaGetSymbolAddress((void**)&h1,      g_h1);
    cudaGetSymbolAddress((void**)&l1,      g_l1);
    cudaGetSymbolAddress((void**)&h2,      g_h2);
    cudaGetSymbolAddress((void**)&l2,      g_l2);
    cudaGetSymbolAddress((void**)&xh,      g_xh);
    cudaGetSymbolAddress((void**)&xl,      g_xl);
    cudaGetSymbolAddress((void**)&finh,    g_finh);
    cudaGetSymbolAddress((void**)&finl,    g_finl);
    cudaGetSymbolAddress((void**)&nh1,     g_nh1);
    cudaGetSymbolAddress((void**)&nl1,     g_nl1);
    cudaGetSymbolAddress((void**)&nh2,     g_nh2);
    cudaGetSymbolAddress((void**)&nl2,     g_nl2);

    cudaFuncSetAttribute((const void*)mlp_mma<128,128>,
                         cudaFuncAttributeMaxDynamicSharedMemorySize, SMEM_P);
    cudaFuncSetAttribute((const void*)mlp_mma<64,64>,
                         cudaFuncAttributeMaxDynamicSharedMemorySize, SMEM_N);

    // 1: zero accumulators + ALL tensor-layer weight splits (one launch,
    //    BEFORE any GEMM consumes them)
    prep_kernel<<<(WREST + 255)/256, 256>>>(fp_w[2], fp_w[3],
                                            fn_w[0], fn_w[1], fn_w[2], fn_w[3]);
    // 2: knn + scatter
    knn_kernel<<<dim3(NPTS/256, BATCH), 256>>>(x, node);
    // 3: fused xdec + L1 + L2 (fp32; writes xh/xl + h2/l2)
    l1x2_kernel<<<PTOT/256, 256>>>(x, fp_w[0], fp_b[0], fp_w[1], fp_b[1]);

    // 4: L3 — the profiled launch (K=128)
    mlp_mma<128,128><<<dim3(PTOT/128, 2), 256, SMEM_P>>>(
        wh + 8192, wl + 8192, 128, fp_b[2],
        h2, l2, 128, h2, l2,
        nullptr, h1, l1, 128, PTOT, 0);
    // 5: L4
    mlp_mma<128,128><<<dim3(PTOT/128, 3), 256, SMEM_P>>>(
        wh + 40960, wl + 40960, 288, fp_b[3],
        h1, l1, 256, xh, xl,
        bufB, nullptr, nullptr, 259, PTOT, 1);

    segmax2_kernel<<<dim3(PTOT/4096, 384/16), 256>>>();
    meanfin_kernel<<<(BATCH*MNODE + 255)/256, 256>>>();
    fallback_kernel<<<(BATCH*MNODE*384 + 255)/256, 256>>>();
    fsplit_kernel<<<(387*P2 + 255)/256, 256>>>(finalin, finh, finl, 387*P2);

    // node resnet, 64x64 tiles
    mlp_mma<64,64><<<dim3(P2/64, 8), 256, SMEM_N>>>(
        wh + 151552, wl + 151552, 416, fn_b[0],
        finh, finl, 387, finh, finl,
        nullptr, nh1, nl1, 387, P2, 0);
    mlp_mma<64,64><<<dim3(P2/64, 8), 256, SMEM_N>>>(
        wh + 364544, wl + 364544, 512, fn_b[1],
        nh1, nl1, 512, nh1, nl1,
        nullptr, nh2, nl2, 512, P2, 0);
    mlp_mma<64,64><<<dim3(P2/64, 12), 256, SMEM_N>>>(
        wh + 626688, wl + 626688, 512, fn_b[2],
        nh2, nl2, 512, nh2, nl2,
        nullptr, nh1, nl1, 512, P2, 0);
    mlp_mma<64,64><<<dim3(P2/64, 16), 256, SMEM_N>>>(
        wh + 1019904, wl + 1019904, 1184, fn_b[3],
        nh1, nl1, 768, finh, finl,
        fnB, nullptr, nullptr, 1155, P2, 1);

    outmax_kernel<<<(BATCH*1024*32 + 255)/256, 256>>>(out);
}

// round 15
// speedup vs baseline: 1.0609x; 1.0609x over previous
#include <cuda_runtime.h>
#include <cuda_bf16.h>
#include <cstdint>

#define NPTS 4096
#define BATCH 8
#define MNODE 256
#define J3N (3*NPTS)            // 12288 stacked points per batch
#define PTOT (BATCH*J3N)        // 98304
#define P2   (BATCH*MNODE)      // 2048

// -------------------- scratch (static device globals; no allocation) -----
__device__ __align__(16) float g_counts[BATCH*MNODE];
__device__ __align__(16) float g_sums[BATCH*3*MNODE];
__device__ __align__(16) int   g_minidx[BATCH*J3N];
__device__ __align__(16) float g_bufB[384*PTOT];       // L4 fp32 out, 151 MB
__device__ __align__(16) float g_finalin[387*P2];
__device__ __align__(16) float g_fnB[1024*P2];
// bf16 hi/lo activation planes
__device__ __align__(16) uint16_t g_h1[256*PTOT], g_l1[256*PTOT];
__device__ __align__(16) uint16_t g_h2[256*PTOT], g_l2[256*PTOT];
__device__ __align__(16) uint16_t g_xh[3*PTOT],   g_xl[3*PTOT];
__device__ __align__(16) uint16_t g_finh[387*P2], g_finl[387*P2];
__device__ __align__(16) uint16_t g_nh1[768*P2],  g_nl1[768*P2];
__device__ __align__(16) uint16_t g_nh2[512*P2],  g_nl2[512*P2];
// bf16 hi/lo weight planes (zero-padded K)
#define WTOT 2232320
__device__ __align__(16) uint16_t g_wh[WTOT];
__device__ __align__(16) uint16_t g_wl[WTOT];

// ==================== helpers ============================================
__device__ __forceinline__ uint32_t smem_u32(const void* p) {
    uint32_t a;
    asm("{ .reg .u64 t; cvta.to.shared.u64 t, %1; cvt.u32.u64 %0, t; }"
        : "=r"(a) : "l"(p));
    return a;
}
#define CPASYNC(saddr, gptr) \
    asm volatile("cp.async.cg.shared.global [%0], [%1], 16;" \
                 :: "r"(saddr), "l"(gptr))
#define CPCOMMIT() asm volatile("cp.async.commit_group;")
#define CPWAIT(N)  asm volatile("cp.async.wait_group %0;" :: "n"(N))

#define LDSM4(r, addr) asm volatile( \
    "ldmatrix.sync.aligned.m8n8.x4.shared.b16 {%0,%1,%2,%3}, [%4];" \
    : "=r"((r)[0]),"=r"((r)[1]),"=r"((r)[2]),"=r"((r)[3]) : "r"(addr))
#define LDSM4T(r, addr) asm volatile( \
    "ldmatrix.sync.aligned.m8n8.x4.trans.shared.b16 {%0,%1,%2,%3}, [%4];" \
    : "=r"((r)[0]),"=r"((r)[1]),"=r"((r)[2]),"=r"((r)[3]) : "r"(addr))
#define MMA_BF16(c, a, b0, b1) asm volatile( \
    "mma.sync.aligned.m16n8k16.row.col.f32.bf16.bf16.f32 " \
    "{%0,%1,%2,%3}, {%4,%5,%6,%7}, {%8,%9}, {%0,%1,%2,%3};" \
    : "+f"((c)[0]),"+f"((c)[1]),"+f"((c)[2]),"+f"((c)[3]) \
    : "r"((a)[0]),"r"((a)[1]),"r"((a)[2]),"r"((a)[3]), "r"(b0),"r"(b1))

__device__ __forceinline__ void split1(float v, uint16_t& h, uint16_t& l) {
    __nv_bfloat16 hb = __float2bfloat16_rn(v);
    h = __bfloat16_as_ushort(hb);
    l = __bfloat16_as_ushort(__float2bfloat16_rn(v - __bfloat162float(hb)));
}

// ==================== prep: zero accumulators + ALL weight splits =========
#define ZTOT (387*P2)
__global__ void prep_kernel(const float* __restrict__ w0,
                            const float* __restrict__ w1,
                            const float* __restrict__ w2, const float* __restrict__ w3,
                            const float* __restrict__ w4, const float* __restrict__ w5,
                            const float* __restrict__ w6)
{
    int i = blockIdx.x * 256 + threadIdx.x;
    if (i < BATCH*MNODE) g_counts[i] = 0.f;
    if (i < BATCH*3*MNODE) g_sums[i] = 0.f;
    if (i < ZTOT) g_finalin[i] = 0.f;
    if (i >= WTOT) return;
    const float* W; int K, Kpad, off;
    if      (i <    8192) { W = w0; K =   64; Kpad =   64; off = 0; }
    else if (i <   40960) { W = w1; K =  128; Kpad =  128; off = 8192; }
    else if (i <  151552) { W = w2; K =  259; Kpad =  288; off = 40960; }
    else if (i <  364544) { W = w3; K =  387; Kpad =  416; off = 151552; }
    else if (i <  626688) { W = w4; K =  512; Kpad =  512; off = 364544; }
    else if (i < 1019904) { W = w5; K =  512; Kpad =  512; off = 626688; }
    else                  { W = w6; K = 1155; Kpad = 1184; off = 1019904; }
    int li = i - off;
    int m = li / Kpad, k = li % Kpad;
    float v = (k < K) ? W[(size_t)m * K + k] : 0.f;
    split1(v, g_wh[i], g_wl[i]);
}

__global__ void fsplit_kernel(const float* __restrict__ X,
                              uint16_t* __restrict__ H, uint16_t* __restrict__ L,
                              int n)
{
    int i = blockIdx.x * 256 + threadIdx.x;
    if (i >= n) return;
    split1(X[i], H[i], L[i]);
}

// ==================== mma.sync bf16 split GEMM (2-stage, 1 sync/tile) =====
// Y[M,P] = relu(W @ X + bias). Tile BM x BN, BK=32. 8 warps as 2 x 4.
// epi: 0 = write hi/lo bf16 planes (Yh/Yl); 1 = write fp32 plane (Yf)
template<int BM, int BN>
__global__ void __launch_bounds__(256, 2)
mlp_mma(const uint16_t* __restrict__ Wh, const uint16_t* __restrict__ Wl, int Kpad,
        const float* __restrict__ bias,
        const uint16_t* __restrict__ XH1, const uint16_t* __restrict__ XL1, int C1,
        const uint16_t* __restrict__ XH2, const uint16_t* __restrict__ XL2,
        float* __restrict__ Yf, uint16_t* __restrict__ Yh, uint16_t* __restrict__ Yl,
        int Kd, int P, int epi)
{
    constexpr int MI = BM / 32;            // m16-frags per warp (warp_m dim 2)
    constexpr int NG = BN / 64;            // LDSM4T groups per plane
    constexpr int NI = 2 * NG;             // n8-frag pairs
    constexpr int APLANE = BM * 80;        // BM*40*2 bytes (stride 40 uint16)
    constexpr int BSTR = BN + 8;           // B row stride in uint16
    constexpr int BPLANE = 32 * BSTR * 2;
    constexpr int BOFF = 2 * APLANE;
    constexpr int STAGE = 2 * APLANE + 2 * BPLANE;
    constexpr int AITER = BM / 64;
    constexpr int BITER = BN / 64;
    constexpr int BCH = BN / 8;            // 16B chunks per B row

    extern __shared__ __align__(16) char dyn[];
    const int tid = threadIdx.x, lane = tid & 31, wid = tid >> 5;
    const int warp_m = wid & 1, warp_n = wid >> 1;   // 2 x 4 warp grid
    const int tile_m = blockIdx.y * BM;
    const int tile_p = blockIdx.x * BN;
    const uint32_t sbase = smem_u32(dyn);

    float acc[MI][NI][4] = {};
    const int nt = Kpad / 32;

    auto fill = [&](int stg, int t) {
        const int k0 = t * 32;
        const uint32_t st = sbase + stg * STAGE;
#pragma unroll
        for (int i = 0; i < AITER; i++) {
            int e = tid + i * 256;
            int m = e >> 2, c = e & 3;
            uint32_t d = st + (uint32_t)(m * 80 + c * 16);
            size_t go = (size_t)(tile_m + m) * Kpad + k0 + c * 8;
            CPASYNC(d, Wh + go);
            CPASYNC(d + APLANE, Wl + go);
        }
#pragma unroll
        for (int i = 0; i < BITER; i++) {
            int e = tid + i * 256;
            int k = e / BCH, c = e % BCH;
            int gk = k0 + k;
            uint32_t d = st + BOFF + (uint32_t)(k * BSTR + c * 8) * 2;
            if (gk < Kd) {
                const uint16_t* sh = ((gk < C1) ? XH1 + (size_t)gk * P
                                                : XH2 + (size_t)(gk - C1) * P)
                                     + tile_p + c * 8;
                const uint16_t* sl = ((gk < C1) ? XL1 + (size_t)gk * P
                                                : XL2 + (size_t)(gk - C1) * P)
                                     + tile_p + c * 8;
                CPASYNC(d, sh);
                CPASYNC(d + BPLANE, sl);
            } else {
                *(uint4*)(dyn + (d - sbase)) = make_uint4(0, 0, 0, 0);
                *(uint4*)(dyn + (d + BPLANE - sbase)) = make_uint4(0, 0, 0, 0);
            }
        }
        CPCOMMIT();
    };

    auto compute = [&](int stg) {
        const uint32_t st = sbase + stg * STAGE;
#pragma unroll
        for (int kc = 0; kc < 32; kc += 16) {
            uint32_t bh[NG][4], bl[NG][4];
            uint32_t brow = (uint32_t)(kc + (lane & 7) + ((lane >> 3) & 1) * 8);
#pragma unroll
            for (int g = 0; g < NG; g++) {
                uint32_t bcol = (uint32_t)(warp_n * (BN/4) + g * 16 + (lane >> 4) * 8);
                uint32_t ba = st + BOFF + (brow * BSTR + bcol) * 2;
                LDSM4T(bh[g], ba);
                LDSM4T(bl[g], ba + BPLANE);
            }
#pragma unroll
            for (int mi = 0; mi < MI; mi++) {
                uint32_t ar = (uint32_t)(warp_m * (BM/2) + mi * 16 + (lane & 15));
                uint32_t ac = (uint32_t)(kc + (lane >> 4) * 8);
                uint32_t aa = st + (ar * 40 + ac) * 2;
                uint32_t ah[4], al[4];
                LDSM4(ah, aa);
                LDSM4(al, aa + APLANE);
#pragma unroll
                for (int ni = 0; ni < NI; ni++) {
                    int g = ni >> 1, x = (ni & 1) * 2;
                    MMA_BF16(acc[mi][ni], ah, bh[g][x], bh[g][x + 1]);
                    MMA_BF16(acc[mi][ni], ah, bl[g][x], bl[g][x + 1]);
                    MMA_BF16(acc[mi][ni], al, bh[g][x], bh[g][x + 1]);
                }
            }
        }
    };

    // 2-stage, single sync per k-tile: the sync at iter t orders
    // compute(t-1) (buffer cur^1) before fill(t+1) overwrites it; CPWAIT(0)
    // + sync makes fill(t)'s data visible to all threads for compute(t).
    fill(0, 0);
    for (int t = 0; t < nt; t++) {
        const int cur = t & 1;
        CPWAIT(0);
        __syncthreads();
        if (t + 1 < nt) fill(cur ^ 1, t + 1);
        compute(cur);
    }

    // ---- epilogue ----
#pragma unroll
    for (int mi = 0; mi < MI; mi++) {
        int gm0 = tile_m + warp_m * (BM/2) + mi * 16 + (lane >> 2);
        float b0 = bias[gm0], b1 = bias[gm0 + 8];
#pragma unroll
        for (int ni = 0; ni < NI; ni++) {
            int gp = tile_p + warp_n * (BN/4) + ni * 8 + (lane & 3) * 2;
            float* c = acc[mi][ni];
            float v00 = fmaxf(c[0] + b0, 0.f), v01 = fmaxf(c[1] + b0, 0.f);
            float v10 = fmaxf(c[2] + b1, 0.f), v11 = fmaxf(c[3] + b1, 0.f);
            if (epi == 1) {
                *(float2*)(Yf + (size_t)gm0 * P + gp) = make_float2(v00, v01);
                *(float2*)(Yf + (size_t)(gm0 + 8) * P + gp) = make_float2(v10, v11);
            } else {
                uint16_t h0, l0, h1_, l1_;
                split1(v00, h0, l0); split1(v01, h1_, l1_);
                *(uint32_t*)(Yh + (size_t)gm0 * P + gp) =
                    (uint32_t)h0 | ((uint32_t)h1_ << 16);
                *(uint32_t*)(Yl + (size_t)gm0 * P + gp) =
                    (uint32_t)l0 | ((uint32_t)l1_ << 16);
                split1(v10, h0, l0); split1(v11, h1_, l1_);
                *(uint32_t*)(Yh + (size_t)(gm0 + 8) * P + gp) =
                    (uint32_t)h0 | ((uint32_t)h1_ << 16);
                *(uint32_t*)(Yl + (size_t)(gm0 + 8) * P + gp) =
                    (uint32_t)l0 | ((uint32_t)l1_ << 16);
            }
        }
    }
}

#define SMEM_P (2*(2*(128*80) + 2*(32*136*2)))
#define SMEM_N (2*(2*(64*80)  + 2*(32*72*2)))

// ==================== KNN + scatter counts/sums ===========================
__global__ void knn_kernel(const float* __restrict__ x,
                           const float* __restrict__ node)
{
    int b = blockIdx.y;
    int n = blockIdx.x * blockDim.x + threadIdx.x;
    __shared__ float s0[MNODE], s1[MNODE], s2[MNODE], sq[MNODE];
    for (int m = threadIdx.x; m < MNODE; m += blockDim.x) {
        float a = node[(b*3+0)*MNODE + m];
        float bb = node[(b*3+1)*MNODE + m];
        float c = node[(b*3+2)*MNODE + m];
        s0[m] = a; s1[m] = bb; s2[m] = c;
        sq[m] = a*a + bb*bb + c*c;
    }
    __syncthreads();
    if (n >= NPTS) return;
    float x0 = x[(b*3+0)*NPTS + n];
    float x1 = x[(b*3+1)*NPTS + n];
    float x2 = x[(b*3+2)*NPTS + n];
    float xx = x0*x0 + x1*x1 + x2*x2;
    float bd0 = 1e30f, bd1 = 1e30f, bd2 = 1e30f;
    int bi0 = 0, bi1 = 0, bi2 = 0;
    for (int m = 0; m < MNODE; m++) {
        float cr = x0*s0[m] + x1*s1[m] + x2*s2[m];
        float d = (xx + sq[m]) - 2.0f*cr;
        if (d < bd0)      { bd2=bd1; bi2=bi1; bd1=bd0; bi1=bi0; bd0=d; bi0=m; }
        else if (d < bd1) { bd2=bd1; bi2=bi1; bd1=d; bi1=m; }
        else if (d < bd2) { bd2=d; bi2=m; }
    }
    int base = b*J3N + n;
    g_minidx[base]          = bi0;
    g_minidx[base + NPTS]   = bi1;
    g_minidx[base + 2*NPTS] = bi2;
    int mm[3] = {bi0, bi1, bi2};
#pragma unroll
    for (int k = 0; k < 3; k++) {
        atomicAdd(&g_counts[b*MNODE + mm[k]], 1.0f);
        atomicAdd(&g_sums[(b*3+0)*MNODE + mm[k]], x0);
        atomicAdd(&g_sums[(b*3+1)*MNODE + mm[k]], x1);
        atomicAdd(&g_sums[(b*3+2)*MNODE + mm[k]], x2);
    }
}

// ==================== fused xdec + L1 (inline mean) =======================
__global__ void l1x_kernel(const float* __restrict__ x,
                           const float* __restrict__ W, const float* __restrict__ B)
{
    __shared__ float w[64*3];
    __shared__ float bb[64];
    int tid = threadIdx.x;
    if (tid < 192) w[tid] = W[tid];
    if (tid < 64) bb[tid] = B[tid];
    __syncthreads();
    int p = blockIdx.x * 256 + tid;
    int b = p / J3N, j = p % J3N, n = j % NPTS;
    int m = g_minidx[p];
    float den = g_counts[b*MNODE + m] + 1e-5f;
    float v0 = x[(b*3+0)*NPTS + n] - g_sums[(b*3+0)*MNODE + m] / den;
    float v1 = x[(b*3+1)*NPTS + n] - g_sums[(b*3+1)*MNODE + m] / den;
    float v2 = x[(b*3+2)*NPTS + n] - g_sums[(b*3+2)*MNODE + m] / den;
    split1(v0, g_xh[p],          g_xl[p]);
    split1(v1, g_xh[PTOT + p],   g_xl[PTOT + p]);
    split1(v2, g_xh[2*PTOT + p], g_xl[2*PTOT + p]);
#pragma unroll
    for (int c = 0; c < 64; c++) {
        float v = fmaf(w[c*3+0], v0, fmaf(w[c*3+1], v1, fmaf(w[c*3+2], v2, bb[c])));
        v = fmaxf(v, 0.f);
        split1(v, g_h1[(size_t)c*PTOT + p], g_l1[(size_t)c*PTOT + p]);
    }
}

// ==================== cluster mean into finalin rows 0..2 =================
__global__ void meanfin_kernel()
{
    int i = blockIdx.x * blockDim.x + threadIdx.x;
    if (i >= BATCH*MNODE) return;
    int b = i / MNODE, m = i % MNODE;
    float den = g_counts[i] + 1e-5f;
#pragma unroll
    for (int c = 0; c < 3; c++)
        g_finalin[c*P2 + i] = g_sums[(b*3+c)*MNODE + m] / den;
}

// ==================== segment max, smem-staged (4096 pts/CTA) =============
__global__ void segmax2_kernel()
{
    __shared__ int sm[MNODE*16];
    int tid = threadIdx.x;
    for (int e = tid; e < MNODE*16; e += 256) sm[e] = 0;
    __syncthreads();
    int c0 = blockIdx.y * 16;
    int pbase = blockIdx.x * 4096;
    int b = pbase / J3N;
    for (int pp = tid; pp < 4096; pp += 256) {
        int p = pbase + pp;
        int m = g_minidx[p];
#pragma unroll
        for (int c = 0; c < 16; c++) {
            float v = g_bufB[(size_t)(c0+c)*PTOT + p];
            atomicMax(&sm[m*16+c], __float_as_int(v));
        }
    }
    __syncthreads();
    for (int e = tid; e < MNODE*16; e += 256) {
        int v = sm[e];
        if (v != 0) {
            int m = e / 16, c = e % 16;
            atomicMax((int*)&g_finalin[(size_t)(3+c0+c)*P2 + b*MNODE + m], v);
        }
    }
}

__global__ void fallback_kernel()
{
    int t = blockIdx.x * blockDim.x + threadIdx.x;
    if (t >= BATCH*MNODE*384) return;
    int c  = t / (BATCH*MNODE);
    int i2 = t % (BATCH*MNODE);
    if (g_counts[i2] > 0.f) return;
    int b = i2 / MNODE;
    g_finalin[(size_t)(3 + c)*P2 + i2] = g_bufB[(size_t)c*PTOT + (size_t)b*J3N];
}

__global__ void outmax_kernel(float* __restrict__ out)
{
    int gt = blockIdx.x * blockDim.x + threadIdx.x;
    int w = gt >> 5;
    int lane = gt & 31;
    if (w >= BATCH*1024) return;
    int b = w / 1024, c = w % 1024;
    const float* src = &g_fnB[(size_t)c*P2 + b*MNODE];
    float v = -1e30f;
#pragma unroll
    for (int i = lane; i < MNODE; i += 32) v = fmaxf(v, src[i]);
#pragma unroll
    for (int o = 16; o > 0; o >>= 1)
        v = fmaxf(v, __shfl_xor_sync(0xffffffffu, v, o));
    if (lane == 0) out[w] = v;
}

// ==========================================================================
extern "C" void kernel_launch(void* const* d_in, const int* in_sizes, int n_in,
                              void* d_out, int out_size)
{
    const float* x    = (const float*)d_in[0];
    const float* node = (const float*)d_in[2];
    const float* fp_w[4] = {(const float*)d_in[4], (const float*)d_in[6],
                            (const float*)d_in[8], (const float*)d_in[10]};
    const float* fp_b[4] = {(const float*)d_in[5], (const float*)d_in[7],
                            (const float*)d_in[9], (const float*)d_in[11]};
    const float* fn_w[4] = {(const float*)d_in[12], (const float*)d_in[14],
                            (const float*)d_in[16], (const float*)d_in[18]};
    const float* fn_b[4] = {(const float*)d_in[13], (const float*)d_in[15],
                            (const float*)d_in[17], (const float*)d_in[19]};
    float* out = (float*)d_out;

    float *finalin, *bufB, *fnB;
    uint16_t *wh, *wl, *h1, *l1, *h2, *l2, *xh, *xl, *finh, *finl;
    uint16_t *nh1, *nl1, *nh2, *nl2;
    cudaGetSymbolAddress((void**)&finalin, g_finalin);
    cudaGetSymbolAddress((void**)&bufB,    g_bufB);
    cudaGetSymbolAddress((void**)&fnB,     g_fnB);
    cudaGetSymbolAddress((void**)&wh,      g_wh);
    cudaGetSymbolAddress((void**)&wl,      g_wl);
    cudaGetSymbolAddress((void**)&h1,      g_h1);
    cudaGetSymbolAddress((void**)&l1,      g_l1);
    cudaGetSymbolAddress((void**)&h2,      g_h2);
    cudaGetSymbolAddress((void**)&l2,      g_l2);
    cudaGetSymbolAddress((void**)&xh,      g_xh);
    cudaGetSymbolAddress((void**)&xl,      g_xl);
    cudaGetSymbolAddress((void**)&finh,    g_finh);
    cudaGetSymbolAddress((void**)&finl,    g_finl);
    cudaGetSymbolAddress((void**)&nh1,     g_nh1);
    cudaGetSymbolAddress((void**)&nl1,     g_nl1);
    cudaGetSymbolAddress((void**)&nh2,     g_nh2);
    cudaGetSymbolAddress((void**)&nl2,     g_nl2);

    cudaFuncSetAttribute((const void*)mlp_mma<128,128>,
                         cudaFuncAttributeMaxDynamicSharedMemorySize, SMEM_P);
    cudaFuncSetAttribute((const void*)mlp_mma<64,64>,
                         cudaFuncAttributeMaxDynamicSharedMemorySize, SMEM_N);

    // 1: zero accumulators + ALL weight splits (before any GEMM)
    prep_kernel<<<(WTOT + 255)/256, 256>>>(fp_w[1], fp_w[2], fp_w[3],
                                           fn_w[0], fn_w[1], fn_w[2], fn_w[3]);
    // 2: knn + scatter
    knn_kernel<<<dim3(NPTS/256, BATCH), 256>>>(x, node);
    // 3: fused xdec + L1 (writes xh/xl + h1/l1)
    l1x_kernel<<<PTOT/256, 256>>>(x, fp_w[0], fp_b[0]);

    // 4: L2 — the profiled launch (K=64, directly comparable to R12)
    mlp_mma<128,128><<<dim3(PTOT/128, 1), 256, SMEM_P>>>(
        wh + 0, wl + 0, 64, fp_b[1],
        h1, l1, 64, h1, l1,
        nullptr, h2, l2, 64, PTOT, 0);
    // 5-6: L3, L4
    mlp_mma<128,128><<<dim3(PTOT/128, 2), 256, SMEM_P>>>(
        wh + 8192, wl + 8192, 128, fp_b[2],
        h2, l2, 128, h2, l2,
        nullptr, h1, l1, 128, PTOT, 0);
    mlp_mma<128,128><<<dim3(PTOT/128, 3), 256, SMEM_P>>>(
        wh + 40960, wl + 40960, 288, fp_b[3],
        h1, l1, 256, xh, xl,
        bufB, nullptr, nullptr, 259, PTOT, 1);

    segmax2_kernel<<<dim3(PTOT/4096, 384/16), 256>>>();
    meanfin_kernel<<<(BATCH*MNODE + 255)/256, 256>>>();
    fallback_kernel<<<(BATCH*MNODE*384 + 255)/256, 256>>>();
    fsplit_kernel<<<(387*P2 + 255)/256, 256>>>(finalin, finh, finl, 387*P2);

    // node resnet, 64x64 tiles
    mlp_mma<64,64><<<dim3(P2/64, 8), 256, SMEM_N>>>(
        wh + 151552, wl + 151552, 416, fn_b[0],
        finh, finl, 387, finh, finl,
        nullptr, nh1, nl1, 387, P2, 0);
    mlp_mma<64,64><<<dim3(P2/64, 8), 256, SMEM_N>>>(
        wh + 364544, wl + 364544, 512, fn_b[1],
        nh1, nl1, 512, nh1, nl1,
        nullptr, nh2, nl2, 512, P2, 0);
    mlp_mma<64,64><<<dim3(P2/64, 12), 256, SMEM_N>>>(
        wh + 626688, wl + 626688, 512, fn_b[2],
        nh2, nl2, 512, nh2, nl2,
        nullptr, nh1, nl1, 512, P2, 0);
    mlp_mma<64,64><<<dim3(P2/64, 16), 256, SMEM_N>>>(
        wh + 1019904, wl + 1019904, 1184, fn_b[3],
        nh1, nl1, 768, finh, finl,
        fnB, nullptr, nullptr, 1155, P2, 1);

    outmax_kernel<<<(BATCH*1024*32 + 255)/256, 256>>>(out);
}

// round 16
// speedup vs baseline: 1.0685x; 1.0071x over previous
#include <cuda_runtime.h>
#include <cuda_bf16.h>
#include <cstdint>

#define NPTS 4096
#define BATCH 8
#define MNODE 256
#define J3N (3*NPTS)            // 12288 stacked points per batch
#define PTOT (BATCH*J3N)        // 98304
#define P2   (BATCH*MNODE)      // 2048

// -------------------- scratch (static device globals; no allocation) -----
__device__ __align__(16) float g_counts[BATCH*MNODE];
__device__ __align__(16) float g_sums[BATCH*3*MNODE];
__device__ __align__(16) int   g_minidx[BATCH*J3N];
__device__ __align__(16) float g_xdec[3*PTOT];         // fp32 (epilogue residual)
__device__ __align__(16) float g_bufB[384*PTOT];       // L4 fp32 out, 151 MB
__device__ __align__(16) float g_finalin[387*P2];
__device__ __align__(16) float g_fnB[1024*P2];
// bf16 hi/lo activation planes
__device__ __align__(16) uint16_t g_h1[256*PTOT], g_l1[256*PTOT];
__device__ __align__(16) uint16_t g_h2[256*PTOT], g_l2[256*PTOT];
__device__ __align__(16) uint16_t g_finh[387*P2], g_finl[387*P2];
__device__ __align__(16) uint16_t g_nh1[768*P2],  g_nl1[768*P2];
__device__ __align__(16) uint16_t g_nh2[512*P2],  g_nl2[512*P2];
// bf16 hi/lo weight planes (zero-padded K); L4 truncated to K=256 (x-residual
// handled in epilogue)
#define WTOT 2220032
__device__ __align__(16) uint16_t g_wh[WTOT];
__device__ __align__(16) uint16_t g_wl[WTOT];

// ==================== helpers ============================================
__device__ __forceinline__ uint32_t smem_u32(const void* p) {
    uint32_t a;
    asm("{ .reg .u64 t; cvta.to.shared.u64 t, %1; cvt.u32.u64 %0, t; }"
        : "=r"(a) : "l"(p));
    return a;
}
#define CPASYNC(saddr, gptr) \
    asm volatile("cp.async.cg.shared.global [%0], [%1], 16;" \
                 :: "r"(saddr), "l"(gptr))
#define CPCOMMIT() asm volatile("cp.async.commit_group;")
#define CPWAIT(N)  asm volatile("cp.async.wait_group %0;" :: "n"(N))

#define LDSM4(r, addr) asm volatile( \
    "ldmatrix.sync.aligned.m8n8.x4.shared.b16 {%0,%1,%2,%3}, [%4];" \
    : "=r"((r)[0]),"=r"((r)[1]),"=r"((r)[2]),"=r"((r)[3]) : "r"(addr))
#define LDSM4T(r, addr) asm volatile( \
    "ldmatrix.sync.aligned.m8n8.x4.trans.shared.b16 {%0,%1,%2,%3}, [%4];" \
    : "=r"((r)[0]),"=r"((r)[1]),"=r"((r)[2]),"=r"((r)[3]) : "r"(addr))
#define MMA_BF16(c, a, b0, b1) asm volatile( \
    "mma.sync.aligned.m16n8k16.row.col.f32.bf16.bf16.f32 " \
    "{%0,%1,%2,%3}, {%4,%5,%6,%7}, {%8,%9}, {%0,%1,%2,%3};" \
    : "+f"((c)[0]),"+f"((c)[1]),"+f"((c)[2]),"+f"((c)[3]) \
    : "r"((a)[0]),"r"((a)[1]),"r"((a)[2]),"r"((a)[3]), "r"(b0),"r"(b1))

__device__ __forceinline__ void split1(float v, uint16_t& h, uint16_t& l) {
    __nv_bfloat16 hb = __float2bfloat16_rn(v);
    h = __bfloat16_as_ushort(hb);
    l = __bfloat16_as_ushort(__float2bfloat16_rn(v - __bfloat162float(hb)));
}

// ==================== prep: zero accumulators + ALL weight splits =========
// L4 (w2): source row stride 259, only first 256 cols split (Kpad=256).
#define ZTOT (387*P2)
__global__ void prep_kernel(const float* __restrict__ w0,
                            const float* __restrict__ w1,
                            const float* __restrict__ w2, const float* __restrict__ w3,
                            const float* __restrict__ w4, const float* __restrict__ w5,
                            const float* __restrict__ w6)
{
    int i = blockIdx.x * 256 + threadIdx.x;
    if (i < BATCH*MNODE) g_counts[i] = 0.f;
    if (i < BATCH*3*MNODE) g_sums[i] = 0.f;
    if (i < ZTOT) g_finalin[i] = 0.f;
    if (i >= WTOT) return;
    const float* W; int K, Kpad, off;
    if      (i <    8192) { W = w0; K =   64; Kpad =   64; off = 0; }
    else if (i <   40960) { W = w1; K =  128; Kpad =  128; off = 8192; }
    else if (i <  139264) { W = w2; K =  259; Kpad =  256; off = 40960; }
    else if (i <  352256) { W = w3; K =  387; Kpad =  416; off = 139264; }
    else if (i <  614400) { W = w4; K =  512; Kpad =  512; off = 352256; }
    else if (i < 1007616) { W = w5; K =  512; Kpad =  512; off = 614400; }
    else                  { W = w6; K = 1155; Kpad = 1184; off = 1007616; }
    int li = i - off;
    int m = li / Kpad, k = li % Kpad;
    float v = (k < K) ? W[(size_t)m * K + k] : 0.f;
    split1(v, g_wh[i], g_wl[i]);
}

// ==================== mma.sync bf16 split GEMM (2-stage, 1 sync/tile) =====
// Y[M,P] = relu(W @ X + bias (+ Wres[:,256:259] @ Xres)). Tile BM x BN.
// epi: 0 = write hi/lo bf16 planes (Yh/Yl); 1 = write fp32 plane (Yf)
template<int BM, int BN>
__global__ void __launch_bounds__(256, 2)
mlp_mma(const uint16_t* __restrict__ Wh, const uint16_t* __restrict__ Wl, int Kpad,
        const float* __restrict__ bias,
        const uint16_t* __restrict__ XH1, const uint16_t* __restrict__ XL1, int C1,
        const uint16_t* __restrict__ XH2, const uint16_t* __restrict__ XL2,
        float* __restrict__ Yf, uint16_t* __restrict__ Yh, uint16_t* __restrict__ Yl,
        const float* __restrict__ Wres, const float* __restrict__ Xres,
        int Kd, int P, int epi)
{
    constexpr int MI = BM / 32;
    constexpr int NG = BN / 64;
    constexpr int NI = 2 * NG;
    constexpr int APLANE = BM * 80;
    constexpr int BSTR = BN + 8;
    constexpr int BPLANE = 32 * BSTR * 2;
    constexpr int BOFF = 2 * APLANE;
    constexpr int STAGE = 2 * APLANE + 2 * BPLANE;
    constexpr int AITER = BM / 64;
    constexpr int BITER = BN / 64;
    constexpr int BCH = BN / 8;

    extern __shared__ __align__(16) char dyn[];
    const int tid = threadIdx.x, lane = tid & 31, wid = tid >> 5;
    const int warp_m = wid & 1, warp_n = wid >> 1;
    const int tile_m = blockIdx.y * BM;
    const int tile_p = blockIdx.x * BN;
    const uint32_t sbase = smem_u32(dyn);

    float acc[MI][NI][4] = {};
    const int nt = Kpad / 32;

    auto fill = [&](int stg, int t) {
        const int k0 = t * 32;
        const uint32_t st = sbase + stg * STAGE;
#pragma unroll
        for (int i = 0; i < AITER; i++) {
            int e = tid + i * 256;
            int m = e >> 2, c = e & 3;
            uint32_t d = st + (uint32_t)(m * 80 + c * 16);
            size_t go = (size_t)(tile_m + m) * Kpad + k0 + c * 8;
            CPASYNC(d, Wh + go);
            CPASYNC(d + APLANE, Wl + go);
        }
#pragma unroll
        for (int i = 0; i < BITER; i++) {
            int e = tid + i * 256;
            int k = e / BCH, c = e % BCH;
            int gk = k0 + k;
            uint32_t d = st + BOFF + (uint32_t)(k * BSTR + c * 8) * 2;
            if (gk < Kd) {
                const uint16_t* sh = ((gk < C1) ? XH1 + (size_t)gk * P
                                                : XH2 + (size_t)(gk - C1) * P)
                                     + tile_p + c * 8;
                const uint16_t* sl = ((gk < C1) ? XL1 + (size_t)gk * P
                                                : XL2 + (size_t)(gk - C1) * P)
                                     + tile_p + c * 8;
                CPASYNC(d, sh);
                CPASYNC(d + BPLANE, sl);
            } else {
                *(uint4*)(dyn + (d - sbase)) = make_uint4(0, 0, 0, 0);
                *(uint4*)(dyn + (d + BPLANE - sbase)) = make_uint4(0, 0, 0, 0);
            }
        }
        CPCOMMIT();
    };

    auto compute = [&](int stg) {
        const uint32_t st = sbase + stg * STAGE;
#pragma unroll
        for (int kc = 0; kc < 32; kc += 16) {
            uint32_t bh[NG][4], bl[NG][4];
            uint32_t brow = (uint32_t)(kc + (lane & 7) + ((lane >> 3) & 1) * 8);
#pragma unroll
            for (int g = 0; g < NG; g++) {
                uint32_t bcol = (uint32_t)(warp_n * (BN/4) + g * 16 + (lane >> 4) * 8);
                uint32_t ba = st + BOFF + (brow * BSTR + bcol) * 2;
                LDSM4T(bh[g], ba);
                LDSM4T(bl[g], ba + BPLANE);
            }
#pragma unroll
            for (int mi = 0; mi < MI; mi++) {
                uint32_t ar = (uint32_t)(warp_m * (BM/2) + mi * 16 + (lane & 15));
                uint32_t ac = (uint32_t)(kc + (lane >> 4) * 8);
                uint32_t aa = st + (ar * 40 + ac) * 2;
                uint32_t ah[4], al[4];
                LDSM4(ah, aa);
                LDSM4(al, aa + APLANE);
#pragma unroll
                for (int ni = 0; ni < NI; ni++) {
                    int g = ni >> 1, x = (ni & 1) * 2;
                    MMA_BF16(acc[mi][ni], ah, bh[g][x], bh[g][x + 1]);
                    MMA_BF16(acc[mi][ni], ah, bl[g][x], bl[g][x + 1]);
                    MMA_BF16(acc[mi][ni], al, bh[g][x], bh[g][x + 1]);
                }
            }
        }
    };

    fill(0, 0);
    for (int t = 0; t < nt; t++) {
        const int cur = t & 1;
        CPWAIT(0);
        __syncthreads();
        if (t + 1 < nt) fill(cur ^ 1, t + 1);
        compute(cur);
    }

    // ---- epilogue ----
    // optional rank-3 residual: x values for this thread's two columns
    float xr[4][2][3];
    if (Wres) {
#pragma unroll
        for (int ni = 0; ni < NI; ni++) {
            int gp = tile_p + warp_n * (BN/4) + ni * 8 + (lane & 3) * 2;
#pragma unroll
            for (int c = 0; c < 3; c++) {
                xr[ni][0][c] = Xres[(size_t)c * P + gp];
                xr[ni][1][c] = Xres[(size_t)c * P + gp + 1];
            }
        }
    }
#pragma unroll
    for (int mi = 0; mi < MI; mi++) {
        int gm0 = tile_m + warp_m * (BM/2) + mi * 16 + (lane >> 2);
        float b0 = bias[gm0], b1 = bias[gm0 + 8];
        float wr0[3], wr1[3];
        if (Wres) {
#pragma unroll
            for (int c = 0; c < 3; c++) {
                wr0[c] = Wres[(size_t)gm0 * 259 + 256 + c];
                wr1[c] = Wres[(size_t)(gm0 + 8) * 259 + 256 + c];
            }
        }
#pragma unroll
        for (int ni = 0; ni < NI; ni++) {
            int gp = tile_p + warp_n * (BN/4) + ni * 8 + (lane & 3) * 2;
            float* c = acc[mi][ni];
            float v00 = c[0] + b0, v01 = c[1] + b0;
            float v10 = c[2] + b1, v11 = c[3] + b1;
            if (Wres) {
#pragma unroll
                for (int q = 0; q < 3; q++) {
                    v00 = fmaf(wr0[q], xr[ni][0][q], v00);
                    v01 = fmaf(wr0[q], xr[ni][1][q], v01);
                    v10 = fmaf(wr1[q], xr[ni][0][q], v10);
                    v11 = fmaf(wr1[q], xr[ni][1][q], v11);
                }
            }
            v00 = fmaxf(v00, 0.f); v01 = fmaxf(v01, 0.f);
            v10 = fmaxf(v10, 0.f); v11 = fmaxf(v11, 0.f);
            if (epi == 1) {
                *(float2*)(Yf + (size_t)gm0 * P + gp) = make_float2(v00, v01);
                *(float2*)(Yf + (size_t)(gm0 + 8) * P + gp) = make_float2(v10, v11);
            } else {
                uint16_t h0, l0, h1_, l1_;
                split1(v00, h0, l0); split1(v01, h1_, l1_);
                *(uint32_t*)(Yh + (size_t)gm0 * P + gp) =
                    (uint32_t)h0 | ((uint32_t)h1_ << 16);
                *(uint32_t*)(Yl + (size_t)gm0 * P + gp) =
                    (uint32_t)l0 | ((uint32_t)l1_ << 16);
                split1(v10, h0, l0); split1(v11, h1_, l1_);
                *(uint32_t*)(Yh + (size_t)(gm0 + 8) * P + gp) =
                    (uint32_t)h0 | ((uint32_t)h1_ << 16);
                *(uint32_t*)(Yl + (size_t)(gm0 + 8) * P + gp) =
                    (uint32_t)l0 | ((uint32_t)l1_ << 16);
            }
        }
    }
}

#define SMEM_P (2*(2*(128*80) + 2*(32*136*2)))
#define SMEM_N (2*(2*(64*80)  + 2*(32*72*2)))

// ==================== KNN + scatter counts/sums ===========================
__global__ void knn_kernel(const float* __restrict__ x,
                           const float* __restrict__ node)
{
    int b = blockIdx.y;
    int n = blockIdx.x * blockDim.x + threadIdx.x;
    __shared__ float s0[MNODE], s1[MNODE], s2[MNODE], sq[MNODE];
    for (int m = threadIdx.x; m < MNODE; m += blockDim.x) {
        float a = node[(b*3+0)*MNODE + m];
        float bb = node[(b*3+1)*MNODE + m];
        float c = node[(b*3+2)*MNODE + m];
        s0[m] = a; s1[m] = bb; s2[m] = c;
        sq[m] = a*a + bb*bb + c*c;
    }
    __syncthreads();
    if (n >= NPTS) return;
    float x0 = x[(b*3+0)*NPTS + n];
    float x1 = x[(b*3+1)*NPTS + n];
    float x2 = x[(b*3+2)*NPTS + n];
    float xx = x0*x0 + x1*x1 + x2*x2;
    float bd0 = 1e30f, bd1 = 1e30f, bd2 = 1e30f;
    int bi0 = 0, bi1 = 0, bi2 = 0;
    for (int m = 0; m < MNODE; m++) {
        float cr = x0*s0[m] + x1*s1[m] + x2*s2[m];
        float d = (xx + sq[m]) - 2.0f*cr;
        if (d < bd0)      { bd2=bd1; bi2=bi1; bd1=bd0; bi1=bi0; bd0=d; bi0=m; }
        else if (d < bd1) { bd2=bd1; bi2=bi1; bd1=d; bi1=m; }
        else if (d < bd2) { bd2=d; bi2=m; }
    }
    int base = b*J3N + n;
    g_minidx[base]          = bi0;
    g_minidx[base + NPTS]   = bi1;
    g_minidx[base + 2*NPTS] = bi2;
    int mm[3] = {bi0, bi1, bi2};
#pragma unroll
    for (int k = 0; k < 3; k++) {
        atomicAdd(&g_counts[b*MNODE + mm[k]], 1.0f);
        atomicAdd(&g_sums[(b*3+0)*MNODE + mm[k]], x0);
        atomicAdd(&g_sums[(b*3+1)*MNODE + mm[k]], x1);
        atomicAdd(&g_sums[(b*3+2)*MNODE + mm[k]], x2);
    }
}

// ==================== fused xdec + L1 (inline mean) =======================
__global__ void l1x_kernel(const float* __restrict__ x,
                           const float* __restrict__ W, const float* __restrict__ B)
{
    __shared__ float w[64*3];
    __shared__ float bb[64];
    int tid = threadIdx.x;
    if (tid < 192) w[tid] = W[tid];
    if (tid < 64) bb[tid] = B[tid];
    __syncthreads();
    int p = blockIdx.x * 256 + tid;
    int b = p / J3N, j = p % J3N, n = j % NPTS;
    int m = g_minidx[p];
    float den = g_counts[b*MNODE + m] + 1e-5f;
    float v0 = x[(b*3+0)*NPTS + n] - g_sums[(b*3+0)*MNODE + m] / den;
    float v1 = x[(b*3+1)*NPTS + n] - g_sums[(b*3+1)*MNODE + m] / den;
    float v2 = x[(b*3+2)*NPTS + n] - g_sums[(b*3+2)*MNODE + m] / den;
    g_xdec[p]          = v0;
    g_xdec[PTOT + p]   = v1;
    g_xdec[2*PTOT + p] = v2;
#pragma unroll
    for (int c = 0; c < 64; c++) {
        float v = fmaf(w[c*3+0], v0, fmaf(w[c*3+1], v1, fmaf(w[c*3+2], v2, bb[c])));
        v = fmaxf(v, 0.f);
        split1(v, g_h1[(size_t)c*PTOT + p], g_l1[(size_t)c*PTOT + p]);
    }
}

// ==================== segment max, smem-staged (4096 pts/CTA) =============
__global__ void segmax2_kernel()
{
    __shared__ int sm[MNODE*16];
    int tid = threadIdx.x;
    for (int e = tid; e < MNODE*16; e += 256) sm[e] = 0;
    __syncthreads();
    int c0 = blockIdx.y * 16;
    int pbase = blockIdx.x * 4096;
    int b = pbase / J3N;
    for (int pp = tid; pp < 4096; pp += 256) {
        int p = pbase + pp;
        int m = g_minidx[p];
#pragma unroll
        for (int c = 0; c < 16; c++) {
            float v = g_bufB[(size_t)(c0+c)*PTOT + p];
            atomicMax(&sm[m*16+c], __float_as_int(v));
        }
    }
    __syncthreads();
    for (int e = tid; e < MNODE*16; e += 256) {
        int v = sm[e];
        if (v != 0) {
            int m = e / 16, c = e % 16;
            atomicMax((int*)&g_finalin[(size_t)(3+c0+c)*P2 + b*MNODE + m], v);
        }
    }
}

// ==================== finfin: mean rows + fallback + split (one launch) ===
__global__ void finfin_kernel()
{
    int i = blockIdx.x * 256 + threadIdx.x;
    if (i >= 387*P2) return;
    int c = i / P2, i2 = i % P2;
    int b = i2 / MNODE, m = i2 % MNODE;
    float v;
    if (c < 3) {
        float den = g_counts[i2] + 1e-5f;
        v = g_sums[(b*3+c)*MNODE + m] / den;
        g_finalin[i] = v;
    } else {
        v = g_finalin[i];
        if (g_counts[i2] <= 0.f) {
            v = g_bufB[(size_t)(c-3)*PTOT + (size_t)b*J3N];
            g_finalin[i] = v;
        }
    }
    split1(v, g_finh[i], g_finl[i]);
}

__global__ void outmax_kernel(float* __restrict__ out)
{
    int gt = blockIdx.x * blockDim.x + threadIdx.x;
    int w = gt >> 5;
    int lane = gt & 31;
    if (w >= BATCH*1024) return;
    int b = w / 1024, c = w % 1024;
    const float* src = &g_fnB[(size_t)c*P2 + b*MNODE];
    float v = -1e30f;
#pragma unroll
    for (int i = lane; i < MNODE; i += 32) v = fmaxf(v, src[i]);
#pragma unroll
    for (int o = 16; o > 0; o >>= 1)
        v = fmaxf(v, __shfl_xor_sync(0xffffffffu, v, o));
    if (lane == 0) out[w] = v;
}

// ==========================================================================
extern "C" void kernel_launch(void* const* d_in, const int* in_sizes, int n_in,
                              void* d_out, int out_size)
{
    const float* x    = (const float*)d_in[0];
    const float* node = (const float*)d_in[2];
    const float* fp_w[4] = {(const float*)d_in[4], (const float*)d_in[6],
                            (const float*)d_in[8], (const float*)d_in[10]};
    const float* fp_b[4] = {(const float*)d_in[5], (const float*)d_in[7],
                            (const float*)d_in[9], (const float*)d_in[11]};
    const float* fn_w[4] = {(const float*)d_in[12], (const float*)d_in[14],
                            (const float*)d_in[16], (const float*)d_in[18]};
    const float* fn_b[4] = {(const float*)d_in[13], (const float*)d_in[15],
                            (const float*)d_in[17], (const float*)d_in[19]};
    float* out = (float*)d_out;

    float *bufB, *fnB, *xdec;
    uint16_t *wh, *wl, *h1, *l1, *h2, *l2, *finh, *finl;
    uint16_t *nh1, *nl1, *nh2, *nl2;
    cudaGetSymbolAddress((void**)&bufB,    g_bufB);
    cudaGetSymbolAddress((void**)&fnB,     g_fnB);
    cudaGetSymbolAddress((void**)&xdec,    g_xdec);
    cudaGetSymbolAddress((void**)&wh,      g_wh);
    cudaGetSymbolAddress((void**)&wl,      g_wl);
    cudaGetSymbolAddress((void**)&h1,      g_h1);
    cudaGetSymbolAddress((void**)&l1,      g_l1);
    cudaGetSymbolAddress((void**)&h2,      g_h2);
    cudaGetSymbolAddress((void**)&l2,      g_l2);
    cudaGetSymbolAddress((void**)&finh,    g_finh);
    cudaGetSymbolAddress((void**)&finl,    g_finl);
    cudaGetSymbolAddress((void**)&nh1,     g_nh1);
    cudaGetSymbolAddress((void**)&nl1,     g_nl1);
    cudaGetSymbolAddress((void**)&nh2,     g_nh2);
    cudaGetSymbolAddress((void**)&nl2,     g_nl2);

    cudaFuncSetAttribute((const void*)mlp_mma<128,128>,
                         cudaFuncAttributeMaxDynamicSharedMemorySize, SMEM_P);
    cudaFuncSetAttribute((const void*)mlp_mma<64,64>,
                         cudaFuncAttributeMaxDynamicSharedMemorySize, SMEM_N);

    // 1: zero accumulators + ALL weight splits
    prep_kernel<<<(WTOT + 255)/256, 256>>>(fp_w[1], fp_w[2], fp_w[3],
                                           fn_w[0], fn_w[1], fn_w[2], fn_w[3]);
    // 2: knn + scatter
    knn_kernel<<<dim3(NPTS/256, BATCH), 256>>>(x, node);
    // 3: fused xdec + L1
    l1x_kernel<<<PTOT/256, 256>>>(x, fp_w[0], fp_b[0]);

    // 4: L2 (profiled slot)
    mlp_mma<128,128><<<dim3(PTOT/128, 1), 256, SMEM_P>>>(
        wh + 0, wl + 0, 64, fp_b[1],
        h1, l1, 64, h1, l1,
        nullptr, h2, l2, nullptr, nullptr, 64, PTOT, 0);
    // 5: L3
    mlp_mma<128,128><<<dim3(PTOT/128, 2), 256, SMEM_P>>>(
        wh + 8192, wl + 8192, 128, fp_b[2],
        h2, l2, 128, h2, l2,
        nullptr, h1, l1, nullptr, nullptr, 128, PTOT, 0);
    // 6: L4 — K=256 GEMM + rank-3 x-residual in epilogue
    mlp_mma<128,128><<<dim3(PTOT/128, 3), 256, SMEM_P>>>(
        wh + 40960, wl + 40960, 256, fp_b[3],
        h1, l1, 256, h1, l1,
        bufB, nullptr, nullptr, fp_w[3], xdec, 256, PTOT, 1);

    segmax2_kernel<<<dim3(PTOT/4096, 384/16), 256>>>();
    finfin_kernel<<<(387*P2 + 255)/256, 256>>>();

    // node resnet, 64x64 tiles
    mlp_mma<64,64><<<dim3(P2/64, 8), 256, SMEM_N>>>(
        wh + 139264, wl + 139264, 416, fn_b[0],
        finh, finl, 387, finh, finl,
        nullptr, nh1, nl1, nullptr, nullptr, 387, P2, 0);
    mlp_mma<64,64><<<dim3(P2/64, 8), 256, SMEM_N>>>(
        wh + 352256, wl + 352256, 512, fn_b[1],
        nh1, nl1, 512, nh1, nl1,
        nullptr, nh2, nl2, nullptr, nullptr, 512, P2, 0);
    mlp_mma<64,64><<<dim3(P2/64, 12), 256, SMEM_N>>>(
        wh + 614400, wl + 614400, 512, fn_b[2],
        nh2, nl2, 512, nh2, nl2,
        nullptr, nh1, nl1, nullptr, nullptr, 512, P2, 0);
    mlp_mma<64,64><<<dim3(P2/64, 16), 256, SMEM_N>>>(
        wh + 1007616, wl + 1007616, 1184, fn_b[3],
        nh1, nl1, 768, finh, finl,
        fnB, nullptr, nullptr, nullptr, nullptr, 1155, P2, 1);

    outmax_kernel<<<(BATCH*1024*32 + 255)/256, 256>>>(out);
}

// round 17
// speedup vs baseline: 1.0762x; 1.0072x over previous
#include <cuda_runtime.h>
#include <cuda_bf16.h>
#include <cstdint>

#define NPTS 4096
#define BATCH 8
#define MNODE 256
#define J3N (3*NPTS)            // 12288 stacked points per batch
#define PTOT (BATCH*J3N)        // 98304
#define P2   (BATCH*MNODE)      // 2048

// -------------------- scratch (static device globals; no allocation) -----
__device__ __align__(16) float g_counts[BATCH*MNODE];
__device__ __align__(16) float g_sums[BATCH*3*MNODE];
__device__ __align__(16) int   g_minidx[BATCH*J3N];
__device__ __align__(16) float g_xdec[3*PTOT];         // fp32 (epilogue residual)
__device__ __align__(16) float g_bufB[384*PTOT];       // L4 fp32 out, 151 MB
__device__ __align__(16) float g_finalin[387*P2];
__device__ __align__(16) float g_fnB[1024*P2];
// bf16 hi/lo activation planes
__device__ __align__(16) uint16_t g_h1[256*PTOT], g_l1[256*PTOT];
__device__ __align__(16) uint16_t g_h2[256*PTOT], g_l2[256*PTOT];
__device__ __align__(16) uint16_t g_finh[387*P2], g_finl[387*P2];
__device__ __align__(16) uint16_t g_nh1[768*P2],  g_nl1[768*P2];
__device__ __align__(16) uint16_t g_nh2[512*P2],  g_nl2[512*P2];
// bf16 hi/lo weight planes (zero-padded K); L4 truncated to K=256
#define WTOT 2220032
__device__ __align__(16) uint16_t g_wh[WTOT];
__device__ __align__(16) uint16_t g_wl[WTOT];

// ==================== helpers ============================================
__device__ __forceinline__ uint32_t smem_u32(const void* p) {
    uint32_t a;
    asm("{ .reg .u64 t; cvta.to.shared.u64 t, %1; cvt.u32.u64 %0, t; }"
        : "=r"(a) : "l"(p));
    return a;
}
#define CPASYNC(saddr, gptr) \
    asm volatile("cp.async.cg.shared.global [%0], [%1], 16;" \
                 :: "r"(saddr), "l"(gptr))
#define CPCOMMIT() asm volatile("cp.async.commit_group;")
#define CPWAIT(N)  asm volatile("cp.async.wait_group %0;" :: "n"(N))

#define LDSM4(r, addr) asm volatile( \
    "ldmatrix.sync.aligned.m8n8.x4.shared.b16 {%0,%1,%2,%3}, [%4];" \
    : "=r"((r)[0]),"=r"((r)[1]),"=r"((r)[2]),"=r"((r)[3]) : "r"(addr))
#define LDSM4T(r, addr) asm volatile( \
    "ldmatrix.sync.aligned.m8n8.x4.trans.shared.b16 {%0,%1,%2,%3}, [%4];" \
    : "=r"((r)[0]),"=r"((r)[1]),"=r"((r)[2]),"=r"((r)[3]) : "r"(addr))
#define MMA_BF16(c, a, b0, b1) asm volatile( \
    "mma.sync.aligned.m16n8k16.row.col.f32.bf16.bf16.f32 " \
    "{%0,%1,%2,%3}, {%4,%5,%6,%7}, {%8,%9}, {%0,%1,%2,%3};" \
    : "+f"((c)[0]),"+f"((c)[1]),"+f"((c)[2]),"+f"((c)[3]) \
    : "r"((a)[0]),"r"((a)[1]),"r"((a)[2]),"r"((a)[3]), "r"(b0),"r"(b1))

__device__ __forceinline__ void split1(float v, uint16_t& h, uint16_t& l) {
    __nv_bfloat16 hb = __float2bfloat16_rn(v);
    h = __bfloat16_as_ushort(hb);
    l = __bfloat16_as_ushort(__float2bfloat16_rn(v - __bfloat162float(hb)));
}

// ==================== prep: zero accumulators + ALL weight splits =========
#define ZTOT (387*P2)
__global__ void prep_kernel(const float* __restrict__ w0,
                            const float* __restrict__ w1,
                            const float* __restrict__ w2, const float* __restrict__ w3,
                            const float* __restrict__ w4, const float* __restrict__ w5,
                            const float* __restrict__ w6)
{
    int i = blockIdx.x * 256 + threadIdx.x;
    if (i < BATCH*MNODE) g_counts[i] = 0.f;
    if (i < BATCH*3*MNODE) g_sums[i] = 0.f;
    if (i < ZTOT) g_finalin[i] = 0.f;
    if (i >= WTOT) return;
    const float* W; int K, Kpad, off;
    if      (i <    8192) { W = w0; K =   64; Kpad =   64; off = 0; }
    else if (i <   40960) { W = w1; K =  128; Kpad =  128; off = 8192; }
    else if (i <  139264) { W = w2; K =  259; Kpad =  256; off = 40960; }
    else if (i <  352256) { W = w3; K =  387; Kpad =  416; off = 139264; }
    else if (i <  614400) { W = w4; K =  512; Kpad =  512; off = 352256; }
    else if (i < 1007616) { W = w5; K =  512; Kpad =  512; off = 614400; }
    else                  { W = w6; K = 1155; Kpad = 1184; off = 1007616; }
    int li = i - off;
    int m = li / Kpad, k = li % Kpad;
    float v = (k < K) ? W[(size_t)m * K + k] : 0.f;
    split1(v, g_wh[i], g_wl[i]);
}

// ==================== mma.sync bf16 split GEMM (2-stage, 1 sync/tile) =====
// Y[M,P] = relu(W @ X + bias (+ Wres[:,256:259] @ Xres)). Tile BM x BN.
// epi: 0 = write hi/lo bf16 planes (Yh/Yl); 1 = write fp32 plane (Yf)
template<int BM, int BN, int NCTA>
__global__ void __launch_bounds__(256, NCTA)
mlp_mma(const uint16_t* __restrict__ Wh, const uint16_t* __restrict__ Wl, int Kpad,
        const float* __restrict__ bias,
        const uint16_t* __restrict__ XH1, const uint16_t* __restrict__ XL1, int C1,
        const uint16_t* __restrict__ XH2, const uint16_t* __restrict__ XL2,
        float* __restrict__ Yf, uint16_t* __restrict__ Yh, uint16_t* __restrict__ Yl,
        const float* __restrict__ Wres, const float* __restrict__ Xres,
        int Kd, int P, int epi)
{
    constexpr int MI = BM / 32;
    constexpr int NG = BN / 64;
    constexpr int NI = 2 * NG;
    constexpr int APLANE = BM * 80;
    constexpr int BSTR = BN + 8;
    constexpr int BPLANE = 32 * BSTR * 2;
    constexpr int BOFF = 2 * APLANE;
    constexpr int STAGE = 2 * APLANE + 2 * BPLANE;
    constexpr int AITER = BM / 64;
    constexpr int BITER = BN / 64;
    constexpr int BCH = BN / 8;

    extern __shared__ __align__(16) char dyn[];
    const int tid = threadIdx.x, lane = tid & 31, wid = tid >> 5;
    const int warp_m = wid & 1, warp_n = wid >> 1;
    const int tile_m = blockIdx.y * BM;
    const int tile_p = blockIdx.x * BN;
    const uint32_t sbase = smem_u32(dyn);

    float acc[MI][NI][4] = {};
    const int nt = Kpad / 32;

    auto fill = [&](int stg, int t) {
        const int k0 = t * 32;
        const uint32_t st = sbase + stg * STAGE;
#pragma unroll
        for (int i = 0; i < AITER; i++) {
            int e = tid + i * 256;
            int m = e >> 2, c = e & 3;
            uint32_t d = st + (uint32_t)(m * 80 + c * 16);
            size_t go = (size_t)(tile_m + m) * Kpad + k0 + c * 8;
            CPASYNC(d, Wh + go);
            CPASYNC(d + APLANE, Wl + go);
        }
#pragma unroll
        for (int i = 0; i < BITER; i++) {
            int e = tid + i * 256;
            int k = e / BCH, c = e % BCH;
            int gk = k0 + k;
            uint32_t d = st + BOFF + (uint32_t)(k * BSTR + c * 8) * 2;
            if (gk < Kd) {
                const uint16_t* sh = ((gk < C1) ? XH1 + (size_t)gk * P
                                                : XH2 + (size_t)(gk - C1) * P)
                                     + tile_p + c * 8;
                const uint16_t* sl = ((gk < C1) ? XL1 + (size_t)gk * P
                                                : XL2 + (size_t)(gk - C1) * P)
                                     + tile_p + c * 8;
                CPASYNC(d, sh);
                CPASYNC(d + BPLANE, sl);
            } else {
                *(uint4*)(dyn + (d - sbase)) = make_uint4(0, 0, 0, 0);
                *(uint4*)(dyn + (d + BPLANE - sbase)) = make_uint4(0, 0, 0, 0);
            }
        }
        CPCOMMIT();
    };

    auto compute = [&](int stg) {
        const uint32_t st = sbase + stg * STAGE;
#pragma unroll
        for (int kc = 0; kc < 32; kc += 16) {
            uint32_t bh[NG][4], bl[NG][4];
            uint32_t brow = (uint32_t)(kc + (lane & 7) + ((lane >> 3) & 1) * 8);
#pragma unroll
            for (int g = 0; g < NG; g++) {
                uint32_t bcol = (uint32_t)(warp_n * (BN/4) + g * 16 + (lane >> 4) * 8);
                uint32_t ba = st + BOFF + (brow * BSTR + bcol) * 2;
                LDSM4T(bh[g], ba);
                LDSM4T(bl[g], ba + BPLANE);
            }
#pragma unroll
            for (int mi = 0; mi < MI; mi++) {
                uint32_t ar = (uint32_t)(warp_m * (BM/2) + mi * 16 + (lane & 15));
                uint32_t ac = (uint32_t)(kc + (lane >> 4) * 8);
                uint32_t aa = st + (ar * 40 + ac) * 2;
                uint32_t ah[4], al[4];
                LDSM4(ah, aa);
                LDSM4(al, aa + APLANE);
#pragma unroll
                for (int ni = 0; ni < NI; ni++) {
                    int g = ni >> 1, x = (ni & 1) * 2;
                    MMA_BF16(acc[mi][ni], ah, bh[g][x], bh[g][x + 1]);
                    MMA_BF16(acc[mi][ni], ah, bl[g][x], bl[g][x + 1]);
                    MMA_BF16(acc[mi][ni], al, bh[g][x], bh[g][x + 1]);
                }
            }
        }
    };

    fill(0, 0);
    for (int t = 0; t < nt; t++) {
        const int cur = t & 1;
        CPWAIT(0);
        __syncthreads();
        if (t + 1 < nt) fill(cur ^ 1, t + 1);
        compute(cur);
    }

    // ---- epilogue ----
    float xr[NI][2][3];
    if (Wres) {
#pragma unroll
        for (int ni = 0; ni < NI; ni++) {
            int gp = tile_p + warp_n * (BN/4) + ni * 8 + (lane & 3) * 2;
#pragma unroll
            for (int c = 0; c < 3; c++) {
                xr[ni][0][c] = Xres[(size_t)c * P + gp];
                xr[ni][1][c] = Xres[(size_t)c * P + gp + 1];
            }
        }
    }
#pragma unroll
    for (int mi = 0; mi < MI; mi++) {
        int gm0 = tile_m + warp_m * (BM/2) + mi * 16 + (lane >> 2);
        float b0 = bias[gm0], b1 = bias[gm0 + 8];
        float wr0[3], wr1[3];
        if (Wres) {
#pragma unroll
            for (int c = 0; c < 3; c++) {
                wr0[c] = Wres[(size_t)gm0 * 259 + 256 + c];
                wr1[c] = Wres[(size_t)(gm0 + 8) * 259 + 256 + c];
            }
        }
#pragma unroll
        for (int ni = 0; ni < NI; ni++) {
            int gp = tile_p + warp_n * (BN/4) + ni * 8 + (lane & 3) * 2;
            float* c = acc[mi][ni];
            float v00 = c[0] + b0, v01 = c[1] + b0;
            float v10 = c[2] + b1, v11 = c[3] + b1;
            if (Wres) {
#pragma unroll
                for (int q = 0; q < 3; q++) {
                    v00 = fmaf(wr0[q], xr[ni][0][q], v00);
                    v01 = fmaf(wr0[q], xr[ni][1][q], v01);
                    v10 = fmaf(wr1[q], xr[ni][0][q], v10);
                    v11 = fmaf(wr1[q], xr[ni][1][q], v11);
                }
            }
            v00 = fmaxf(v00, 0.f); v01 = fmaxf(v01, 0.f);
            v10 = fmaxf(v10, 0.f); v11 = fmaxf(v11, 0.f);
            if (epi == 1) {
                *(float2*)(Yf + (size_t)gm0 * P + gp) = make_float2(v00, v01);
                *(float2*)(Yf + (size_t)(gm0 + 8) * P + gp) = make_float2(v10, v11);
            } else {
                uint16_t h0, l0, h1_, l1_;
                split1(v00, h0, l0); split1(v01, h1_, l1_);
                *(uint32_t*)(Yh + (size_t)gm0 * P + gp) =
                    (uint32_t)h0 | ((uint32_t)h1_ << 16);
                *(uint32_t*)(Yl + (size_t)gm0 * P + gp) =
                    (uint32_t)l0 | ((uint32_t)l1_ << 16);
                split1(v10, h0, l0); split1(v11, h1_, l1_);
                *(uint32_t*)(Yh + (size_t)(gm0 + 8) * P + gp) =
                    (uint32_t)h0 | ((uint32_t)h1_ << 16);
                *(uint32_t*)(Yl + (size_t)(gm0 + 8) * P + gp) =
                    (uint32_t)l0 | ((uint32_t)l1_ << 16);
            }
        }
    }
}

#define SMEM_P64 (2*(2*(64*80) + 2*(32*136*2)))   // 55296, 3 CTAs/SM
#define SMEM_N   (2*(2*(64*80) + 2*(32*72*2)))

// ==================== KNN + scatter counts/sums ===========================
__global__ void knn_kernel(const float* __restrict__ x,
                           const float* __restrict__ node)
{
    int b = blockIdx.y;
    int n = blockIdx.x * blockDim.x + threadIdx.x;
    __shared__ float s0[MNODE], s1[MNODE], s2[MNODE], sq[MNODE];
    for (int m = threadIdx.x; m < MNODE; m += blockDim.x) {
        float a = node[(b*3+0)*MNODE + m];
        float bb = node[(b*3+1)*MNODE + m];
        float c = node[(b*3+2)*MNODE + m];
        s0[m] = a; s1[m] = bb; s2[m] = c;
        sq[m] = a*a + bb*bb + c*c;
    }
    __syncthreads();
    if (n >= NPTS) return;
    float x0 = x[(b*3+0)*NPTS + n];
    float x1 = x[(b*3+1)*NPTS + n];
    float x2 = x[(b*3+2)*NPTS + n];
    float xx = x0*x0 + x1*x1 + x2*x2;
    float bd0 = 1e30f, bd1 = 1e30f, bd2 = 1e30f;
    int bi0 = 0, bi1 = 0, bi2 = 0;
    for (int m = 0; m < MNODE; m++) {
        float cr = x0*s0[m] + x1*s1[m] + x2*s2[m];
        float d = (xx + sq[m]) - 2.0f*cr;
        if (d < bd0)      { bd2=bd1; bi2=bi1; bd1=bd0; bi1=bi0; bd0=d; bi0=m; }
        else if (d < bd1) { bd2=bd1; bi2=bi1; bd1=d; bi1=m; }
        else if (d < bd2) { bd2=d; bi2=m; }
    }
    int base = b*J3N + n;
    g_minidx[base]          = bi0;
    g_minidx[base + NPTS]   = bi1;
    g_minidx[base + 2*NPTS] = bi2;
    int mm[3] = {bi0, bi1, bi2};
#pragma unroll
    for (int k = 0; k < 3; k++) {
        atomicAdd(&g_counts[b*MNODE + mm[k]], 1.0f);
        atomicAdd(&g_sums[(b*3+0)*MNODE + mm[k]], x0);
        atomicAdd(&g_sums[(b*3+1)*MNODE + mm[k]], x1);
        atomicAdd(&g_sums[(b*3+2)*MNODE + mm[k]], x2);
    }
}

// ==================== fused xdec + L1 (inline mean) =======================
__global__ void l1x_kernel(const float* __restrict__ x,
                           const float* __restrict__ W, const float* __restrict__ B)
{
    __shared__ float w[64*3];
    __shared__ float bb[64];
    int tid = threadIdx.x;
    if (tid < 192) w[tid] = W[tid];
    if (tid < 64) bb[tid] = B[tid];
    __syncthreads();
    int p = blockIdx.x * 256 + tid;
    int b = p / J3N, j = p % J3N, n = j % NPTS;
    int m = g_minidx[p];
    float den = g_counts[b*MNODE + m] + 1e-5f;
    float v0 = x[(b*3+0)*NPTS + n] - g_sums[(b*3+0)*MNODE + m] / den;
    float v1 = x[(b*3+1)*NPTS + n] - g_sums[(b*3+1)*MNODE + m] / den;
    float v2 = x[(b*3+2)*NPTS + n] - g_sums[(b*3+2)*MNODE + m] / den;
    g_xdec[p]          = v0;
    g_xdec[PTOT + p]   = v1;
    g_xdec[2*PTOT + p] = v2;
#pragma unroll
    for (int c = 0; c < 64; c++) {
        float v = fmaf(w[c*3+0], v0, fmaf(w[c*3+1], v1, fmaf(w[c*3+2], v2, bb[c])));
        v = fmaxf(v, 0.f);
        split1(v, g_h1[(size_t)c*PTOT + p], g_l1[(size_t)c*PTOT + p]);
    }
}

// ==================== segment max, smem-staged (4096 pts/CTA) =============
__global__ void segmax2_kernel()
{
    __shared__ int sm[MNODE*16];
    int tid = threadIdx.x;
    for (int e = tid; e < MNODE*16; e += 256) sm[e] = 0;
    __syncthreads();
    int c0 = blockIdx.y * 16;
    int pbase = blockIdx.x * 4096;
    int b = pbase / J3N;
    for (int pp = tid; pp < 4096; pp += 256) {
        int p = pbase + pp;
        int m = g_minidx[p];
#pragma unroll
        for (int c = 0; c < 16; c++) {
            float v = g_bufB[(size_t)(c0+c)*PTOT + p];
            atomicMax(&sm[m*16+c], __float_as_int(v));
        }
    }
    __syncthreads();
    for (int e = tid; e < MNODE*16; e += 256) {
        int v = sm[e];
        if (v != 0) {
            int m = e / 16, c = e % 16;
            atomicMax((int*)&g_finalin[(size_t)(3+c0+c)*P2 + b*MNODE + m], v);
        }
    }
}

// ==================== finfin: mean rows + fallback + split (one launch) ===
__global__ void finfin_kernel()
{
    int i = blockIdx.x * 256 + threadIdx.x;
    if (i >= 387*P2) return;
    int c = i / P2, i2 = i % P2;
    int b = i2 / MNODE, m = i2 % MNODE;
    float v;
    if (c < 3) {
        float den = g_counts[i2] + 1e-5f;
        v = g_sums[(b*3+c)*MNODE + m] / den;
        g_finalin[i] = v;
    } else {
        v = g_finalin[i];
        if (g_counts[i2] <= 0.f) {
            v = g_bufB[(size_t)(c-3)*PTOT + (size_t)b*J3N];
            g_finalin[i] = v;
        }
    }
    split1(v, g_finh[i], g_finl[i]);
}

__global__ void outmax_kernel(float* __restrict__ out)
{
    int gt = blockIdx.x * blockDim.x + threadIdx.x;
    int w = gt >> 5;
    int lane = gt & 31;
    if (w >= BATCH*1024) return;
    int b = w / 1024, c = w % 1024;
    const float* src = &g_fnB[(size_t)c*P2 + b*MNODE];
    float v = -1e30f;
#pragma unroll
    for (int i = lane; i < MNODE; i += 32) v = fmaxf(v, src[i]);
#pragma unroll
    for (int o = 16; o > 0; o >>= 1)
        v = fmaxf(v, __shfl_xor_sync(0xffffffffu, v, o));
    if (lane == 0) out[w] = v;
}

// ==========================================================================
extern "C" void kernel_launch(void* const* d_in, const int* in_sizes, int n_in,
                              void* d_out, int out_size)
{
    const float* x    = (const float*)d_in[0];
    const float* node = (const float*)d_in[2];
    const float* fp_w[4] = {(const float*)d_in[4], (const float*)d_in[6],
                            (const float*)d_in[8], (const float*)d_in[10]};
    const float* fp_b[4] = {(const float*)d_in[5], (const float*)d_in[7],
                            (const float*)d_in[9], (const float*)d_in[11]};
    const float* fn_w[4] = {(const float*)d_in[12], (const float*)d_in[14],
                            (const float*)d_in[16], (const float*)d_in[18]};
    const float* fn_b[4] = {(const float*)d_in[13], (const float*)d_in[15],
                            (const float*)d_in[17], (const float*)d_in[19]};
    float* out = (float*)d_out;

    float *bufB, *fnB, *xdec;
    uint16_t *wh, *wl, *h1, *l1, *h2, *l2, *finh, *finl;
    uint16_t *nh1, *nl1, *nh2, *nl2;
    cudaGetSymbolAddress((void**)&bufB,    g_bufB);
    cudaGetSymbolAddress((void**)&fnB,     g_fnB);
    cudaGetSymbolAddress((void**)&xdec,    g_xdec);
    cudaGetSymbolAddress((void**)&wh,      g_wh);
    cudaGetSymbolAddress((void**)&wl,      g_wl);
    cudaGetSymbolAddress((void**)&h1,      g_h1);
    cudaGetSymbolAddress((void**)&l1,      g_l1);
    cudaGetSymbolAddress((void**)&h2,      g_h2);
    cudaGetSymbolAddress((void**)&l2,      g_l2);
    cudaGetSymbolAddress((void**)&finh,    g_finh);
    cudaGetSymbolAddress((void**)&finl,    g_finl);
    cudaGetSymbolAddress((void**)&nh1,     g_nh1);
    cudaGetSymbolAddress((void**)&nl1,     g_nl1);
    cudaGetSymbolAddress((void**)&nh2,     g_nh2);
    cudaGetSymbolAddress((void**)&nl2,     g_nl2);

    cudaFuncSetAttribute((const void*)mlp_mma<64,128,3>,
                         cudaFuncAttributeMaxDynamicSharedMemorySize, SMEM_P64);
    cudaFuncSetAttribute((const void*)mlp_mma<64,64,2>,
                         cudaFuncAttributeMaxDynamicSharedMemorySize, SMEM_N);

    // 1: zero accumulators + ALL weight splits
    prep_kernel<<<(WTOT + 255)/256, 256>>>(fp_w[1], fp_w[2], fp_w[3],
                                           fn_w[0], fn_w[1], fn_w[2], fn_w[3]);
    // 2: knn + scatter
    knn_kernel<<<dim3(NPTS/256, BATCH), 256>>>(x, node);
    // 3: fused xdec + L1
    l1x_kernel<<<PTOT/256, 256>>>(x, fp_w[0], fp_b[0]);

    // 4: L2 (profiled slot) — 64x128 tiles, 3 CTAs/SM
    mlp_mma<64,128,3><<<dim3(PTOT/128, 2), 256, SMEM_P64>>>(
        wh + 0, wl + 0, 64, fp_b[1],
        h1, l1, 64, h1, l1,
        nullptr, h2, l2, nullptr, nullptr, 64, PTOT, 0);
    // 5: L3
    mlp_mma<64,128,3><<<dim3(PTOT/128, 4), 256, SMEM_P64>>>(
        wh + 8192, wl + 8192, 128, fp_b[2],
        h2, l2, 128, h2, l2,
        nullptr, h1, l1, nullptr, nullptr, 128, PTOT, 0);
    // 6: L4 — K=256 GEMM + rank-3 x-residual in epilogue
    mlp_mma<64,128,3><<<dim3(PTOT/128, 6), 256, SMEM_P64>>>(
        wh + 40960, wl + 40960, 256, fp_b[3],
        h1, l1, 256, h1, l1,
        bufB, nullptr, nullptr, fp_w[3], xdec, 256, PTOT, 1);

    segmax2_kernel<<<dim3(PTOT/4096, 384/16), 256>>>();
    finfin_kernel<<<(387*P2 + 255)/256, 256>>>();

    // node resnet, 64x64 tiles
    mlp_mma<64,64,2><<<dim3(P2/64, 8), 256, SMEM_N>>>(
        wh + 139264, wl + 139264, 416, fn_b[0],
        finh, finl, 387, finh, finl,
        nullptr, nh1, nl1, nullptr, nullptr, 387, P2, 0);
    mlp_mma<64,64,2><<<dim3(P2/64, 8), 256, SMEM_N>>>(
        wh + 352256, wl + 352256, 512, fn_b[1],
        nh1, nl1, 512, nh1, nl1,
        nullptr, nh2, nl2, nullptr, nullptr, 512, P2, 0);
    mlp_mma<64,64,2><<<dim3(P2/64, 12), 256, SMEM_N>>>(
        wh + 614400, wl + 614400, 512, fn_b[2],
        nh2, nl2, 512, nh2, nl2,
        nullptr, nh1, nl1, nullptr, nullptr, 512, P2, 0);
    mlp_mma<64,64,2><<<dim3(P2/64, 16), 256, SMEM_N>>>(
        wh + 1007616, wl + 1007616, 1184, fn_b[3],
        nh1, nl1, 768, finh, finl,
        fnB, nullptr, nullptr, nullptr, nullptr, 1155, P2, 1);

    outmax_kernel<<<(BATCH*1024*32 + 255)/256, 256>>>(out);
}